// round 6
// baseline (speedup 1.0000x reference)
#include <cuda_runtime.h>
#include <cuda_bf16.h>
#include <cstdint>

#define Bdim 4
#define Nseq 2048
#define Dmod 512
#define Hn   8
#define En   64
#define Mtot (Bdim*Nseq)
#define BHNE ((size_t)Bdim*Hn*Nseq*En)

__device__ float g_xn [(size_t)Mtot*Dmod];
__device__ float g_q  [BHNE];
__device__ float g_k  [BHNE];
__device__ float g_v  [BHNE];
__device__ float g_g  [BHNE];
__device__ float g_att[(size_t)Mtot*Dmod];
__device__ float g_tmp[(size_t)Mtot*Dmod];

// =============== helpers ===============
__device__ __forceinline__ void mma_bf16(float* c, const uint32_t* a, const uint32_t* b) {
    asm volatile("mma.sync.aligned.m16n8k16.row.col.f32.bf16.bf16.f32 "
        "{%0,%1,%2,%3}, {%4,%5,%6,%7}, {%8,%9}, {%0,%1,%2,%3};"
        : "+f"(c[0]), "+f"(c[1]), "+f"(c[2]), "+f"(c[3])
        : "r"(a[0]), "r"(a[1]), "r"(a[2]), "r"(a[3]), "r"(b[0]), "r"(b[1]));
}
__device__ __forceinline__ uint32_t packbf(__nv_bfloat16 lo, __nv_bfloat16 hi) {
    return ((uint32_t)__bfloat16_as_ushort(hi) << 16) | __bfloat16_as_ushort(lo);
}

#define ATT_T 4608   // 64 rows * 72 bf16 per staged tile
#define ATT_SMEM (6*ATT_T*2 + 256)

// ---------- warp-MMA flash attention (unchanged from R5) ----------
__global__ __launch_bounds__(128) void attn_mma(
    const float* __restrict__ Q, const float* __restrict__ K,
    const float* __restrict__ V, const float* __restrict__ G,
    const float* __restrict__ mask, float* __restrict__ out)
{
    extern __shared__ __nv_bfloat16 smb[];
    __nv_bfloat16 *Qh = smb,           *Ql = smb + ATT_T,
                  *Kh = smb + 2*ATT_T, *Kl = smb + 3*ATT_T,
                  *Vh = smb + 4*ATT_T, *Vl = smb + 5*ATT_T;   // Vh/Vl TRANSPOSED: [e][key]
    float* bias = (float*)(smb + 6*ATT_T);

    const int tid = threadIdx.x, wid = tid >> 5, lid = tid & 31;
    const int g = lid >> 2, qp = (lid & 3) * 2;
    const int qt = blockIdx.x, bh = blockIdx.y, bb = bh >> 3, hh = bh & 7;

    const float* Qg = Q + ((size_t)bh * Nseq + (size_t)qt * 64) * 64;
    const float* Kg = K + (size_t)bh * Nseq * 64;
    const float* Vg = V + (size_t)bh * Nseq * 64;

    for (int idx = tid; idx < 64 * 32; idx += 128) {
        int r = idx >> 5, cp = (idx & 31) * 2;
        float2 f = *(const float2*)(Qg + (size_t)r * 64 + cp);
        __nv_bfloat16 h0 = __float2bfloat16_rn(f.x), h1 = __float2bfloat16_rn(f.y);
        __nv_bfloat16 e0 = __float2bfloat16_rn(f.x - __bfloat162float(h0));
        __nv_bfloat16 e1 = __float2bfloat16_rn(f.y - __bfloat162float(h1));
        *(uint32_t*)(Qh + r * 72 + cp) = packbf(h0, h1);
        *(uint32_t*)(Ql + r * 72 + cp) = packbf(e0, e1);
    }
    __syncthreads();

    uint32_t qfh[4][4], qfl[4][4];
    {
        int ar = wid * 16 + g;
        #pragma unroll
        for (int kk = 0; kk < 4; kk++) {
            int c0 = kk * 16 + qp;
            qfh[kk][0] = *(const uint32_t*)(Qh + ar * 72 + c0);
            qfh[kk][1] = *(const uint32_t*)(Qh + (ar + 8) * 72 + c0);
            qfh[kk][2] = *(const uint32_t*)(Qh + ar * 72 + c0 + 8);
            qfh[kk][3] = *(const uint32_t*)(Qh + (ar + 8) * 72 + c0 + 8);
            qfl[kk][0] = *(const uint32_t*)(Ql + ar * 72 + c0);
            qfl[kk][1] = *(const uint32_t*)(Ql + (ar + 8) * 72 + c0);
            qfl[kk][2] = *(const uint32_t*)(Ql + ar * 72 + c0 + 8);
            qfl[kk][3] = *(const uint32_t*)(Ql + (ar + 8) * 72 + c0 + 8);
        }
    }

    float O[8][4];
    #pragma unroll
    for (int i = 0; i < 8; i++) { O[i][0]=0.f; O[i][1]=0.f; O[i][2]=0.f; O[i][3]=0.f; }
    float ps0 = 0.f, ps1 = 0.f;

    for (int t = 0; t < 32; t++) {
        __syncthreads();
        const float* Ks = Kg + (size_t)t * 64 * 64;
        const float* Vs = Vg + (size_t)t * 64 * 64;
        for (int idx = tid; idx < 64 * 32; idx += 128) {
            int r = idx >> 5, cp = (idx & 31) * 2;
            float2 f = *(const float2*)(Ks + (size_t)r * 64 + cp);
            __nv_bfloat16 h0 = __float2bfloat16_rn(f.x), h1 = __float2bfloat16_rn(f.y);
            __nv_bfloat16 e0 = __float2bfloat16_rn(f.x - __bfloat162float(h0));
            __nv_bfloat16 e1 = __float2bfloat16_rn(f.y - __bfloat162float(h1));
            *(uint32_t*)(Kh + r * 72 + cp) = packbf(h0, h1);
            *(uint32_t*)(Kl + r * 72 + cp) = packbf(e0, e1);
            float2 v = *(const float2*)(Vs + (size_t)r * 64 + cp);
            __nv_bfloat16 vh0 = __float2bfloat16_rn(v.x), vh1 = __float2bfloat16_rn(v.y);
            __nv_bfloat16 ve0 = __float2bfloat16_rn(v.x - __bfloat162float(vh0));
            __nv_bfloat16 ve1 = __float2bfloat16_rn(v.y - __bfloat162float(vh1));
            Vh[cp * 72 + r] = vh0; Vh[(cp + 1) * 72 + r] = vh1;
            Vl[cp * 72 + r] = ve0; Vl[(cp + 1) * 72 + r] = ve1;
        }
        if (tid < 64)
            bias[tid] = (mask[bb * Nseq + t * 64 + tid] > 0.f) ? 0.f : -1e9f;
        __syncthreads();

        float cS[8][4];
        #pragma unroll
        for (int i = 0; i < 8; i++) { cS[i][0]=0.f; cS[i][1]=0.f; cS[i][2]=0.f; cS[i][3]=0.f; }
        #pragma unroll
        for (int nt = 0; nt < 8; nt++) {
            int kb = (nt * 8 + g) * 72 + qp;
            #pragma unroll
            for (int kk = 0; kk < 4; kk++) {
                uint32_t b2h[2], b2l[2];
                const __nv_bfloat16* kp = Kh + kb + kk * 16;
                b2h[0] = *(const uint32_t*)kp; b2h[1] = *(const uint32_t*)(kp + 8);
                kp = Kl + kb + kk * 16;
                b2l[0] = *(const uint32_t*)kp; b2l[1] = *(const uint32_t*)(kp + 8);
                mma_bf16(cS[nt], qfh[kk], b2h);
                mma_bf16(cS[nt], qfh[kk], b2l);
                mma_bf16(cS[nt], qfl[kk], b2h);
            }
        }

        uint32_t ahi[4][4], alo[4][4];
        #pragma unroll
        for (int nt = 0; nt < 8; nt++) {
            float b0 = bias[nt * 8 + qp], b1 = bias[nt * 8 + qp + 1];
            float p0 = __expf(fmaf(cS[nt][0], 0.125f, b0));
            float p1 = __expf(fmaf(cS[nt][1], 0.125f, b1));
            float p2 = __expf(fmaf(cS[nt][2], 0.125f, b0));
            float p3 = __expf(fmaf(cS[nt][3], 0.125f, b1));
            ps0 += p0 + p1; ps1 += p2 + p3;
            __nv_bfloat16 h0 = __float2bfloat16_rn(p0), h1 = __float2bfloat16_rn(p1);
            __nv_bfloat16 h2 = __float2bfloat16_rn(p2), h3 = __float2bfloat16_rn(p3);
            __nv_bfloat16 l0 = __float2bfloat16_rn(p0 - __bfloat162float(h0));
            __nv_bfloat16 l1 = __float2bfloat16_rn(p1 - __bfloat162float(h1));
            __nv_bfloat16 l2 = __float2bfloat16_rn(p2 - __bfloat162float(h2));
            __nv_bfloat16 l3 = __float2bfloat16_rn(p3 - __bfloat162float(h3));
            int kk = nt >> 1, o = (nt & 1) * 2;
            ahi[kk][o]     = packbf(h0, h1);
            ahi[kk][o + 1] = packbf(h2, h3);
            alo[kk][o]     = packbf(l0, l1);
            alo[kk][o + 1] = packbf(l2, l3);
        }

        #pragma unroll
        for (int nt = 0; nt < 8; nt++) {
            int vb = (nt * 8 + g) * 72 + qp;
            #pragma unroll
            for (int kk = 0; kk < 4; kk++) {
                uint32_t b2h[2], b2l[2];
                const __nv_bfloat16* vp = Vh + vb + kk * 16;
                b2h[0] = *(const uint32_t*)vp; b2h[1] = *(const uint32_t*)(vp + 8);
                vp = Vl + vb + kk * 16;
                b2l[0] = *(const uint32_t*)vp; b2l[1] = *(const uint32_t*)(vp + 8);
                mma_bf16(O[nt], ahi[kk], b2h);
                mma_bf16(O[nt], ahi[kk], b2l);
                mma_bf16(O[nt], alo[kk], b2h);
            }
        }
    }

    ps0 += __shfl_xor_sync(0xffffffffu, ps0, 1);
    ps0 += __shfl_xor_sync(0xffffffffu, ps0, 2);
    ps1 += __shfl_xor_sync(0xffffffffu, ps1, 1);
    ps1 += __shfl_xor_sync(0xffffffffu, ps1, 2);

    int n0 = qt * 64 + wid * 16 + g, n1 = n0 + 8;
    float qm0 = (mask[bb * Nseq + n0] > 0.f) ? 1.f : 0.f;
    float qm1 = (mask[bb * Nseq + n1] > 0.f) ? 1.f : 0.f;
    float rc0 = (ps0 > 0.f) ? qm0 / ps0 : 0.f;
    float rc1 = (ps1 > 0.f) ? qm1 / ps1 : 0.f;

    const float* G0 = G + ((size_t)bh * Nseq + n0) * 64;
    const float* G1 = G + ((size_t)bh * Nseq + n1) * 64;
    float* O0 = out + ((size_t)bb * Nseq + n0) * Dmod + hh * 64;
    float* O1 = out + ((size_t)bb * Nseq + n1) * Dmod + hh * 64;
    #pragma unroll
    for (int nt = 0; nt < 8; nt++) {
        int col = nt * 8 + qp;
        float2 g0 = *(const float2*)(G0 + col);
        float2 g1 = *(const float2*)(G1 + col);
        float2 w0, w1;
        w0.x = O[nt][0] * rc0 * g0.x; w0.y = O[nt][1] * rc0 * g0.y;
        w1.x = O[nt][2] * rc1 * g1.x; w1.y = O[nt][3] * rc1 * g1.y;
        *(float2*)(O0 + col) = w0;
        *(float2*)(O1 + col) = w1;
    }
}

// ---------------- LayerNorm ----------------
__global__ void ln_kernel(const float* __restrict__ in,
                          const float* __restrict__ gamma,
                          const float* __restrict__ beta,
                          float* __restrict__ out)
{
    int row = blockIdx.x;
    int tid = threadIdx.x;
    const float4 v = ((const float4*)(in + (size_t)row * Dmod))[tid];
    __shared__ float red[4];

    float s = v.x + v.y + v.z + v.w;
    #pragma unroll
    for (int off = 16; off; off >>= 1) s += __shfl_xor_sync(0xffffffffu, s, off);
    if ((tid & 31) == 0) red[tid >> 5] = s;
    __syncthreads();
    float mean = (red[0] + red[1] + red[2] + red[3]) * (1.f / 512.f);

    float dx0 = v.x - mean, dx1 = v.y - mean, dx2 = v.z - mean, dx3 = v.w - mean;
    float ss = dx0*dx0 + dx1*dx1 + dx2*dx2 + dx3*dx3;
    __syncthreads();
    #pragma unroll
    for (int off = 16; off; off >>= 1) ss += __shfl_xor_sync(0xffffffffu, ss, off);
    if ((tid & 31) == 0) red[tid >> 5] = ss;
    __syncthreads();
    float var = (red[0] + red[1] + red[2] + red[3]) * (1.f / 512.f);
    float rstd = rsqrtf(var + 1e-6f);

    const float4 gm = ((const float4*)gamma)[tid];
    const float4 bt = ((const float4*)beta)[tid];
    float4 r;
    r.x = gm.x * dx0 * rstd + bt.x;
    r.y = gm.y * dx1 * rstd + bt.y;
    r.z = gm.z * dx2 * rstd + bt.z;
    r.w = gm.w * dx3 * rstd + bt.w;
    ((float4*)(out + (size_t)row * Dmod))[tid] = r;
}

// ---------------- Projection GEMM: k-major A smem, all-float4 LDS ----------------
// 64x64 tile, K-chunk 32, 256 threads, 4x4 per thread.
__global__ __launch_bounds__(256) void proj_gemm(
    const float* __restrict__ A, const float* __restrict__ W,
    float* __restrict__ out, int mode)
{
    __shared__ float Asm[32 * 68];   // [kk][m], stride 68 (16B-aligned rows)
    __shared__ float Bs [32 * 68];   // [kk][n]
    int tid  = threadIdx.x;
    int m0   = blockIdx.x * 64;
    int head = blockIdx.y;
    int tm = (tid >> 4) << 2;
    int tn = (tid & 15) << 2;
    float c[4][4] = {};

    for (int k0 = 0; k0 < Dmod; k0 += 32) {
        __syncthreads();
        #pragma unroll
        for (int l = 0; l < 8; l++) {
            int idx = l * 256 + tid;
            int am = idx >> 5, ak = idx & 31;                 // gmem coalesced over ak
            Asm[ak * 68 + am] = A[(size_t)(m0 + am) * Dmod + k0 + ak];
            int bk = idx >> 6, bn = idx & 63;                 // gmem coalesced over bn
            Bs[bk * 68 + bn] = W[(size_t)head * Dmod * En + (size_t)(k0 + bk) * En + bn];
        }
        __syncthreads();
        #pragma unroll
        for (int kk = 0; kk < 32; kk++) {
            float4 a = *(const float4*)&Asm[kk * 68 + tm];
            float4 b = *(const float4*)&Bs [kk * 68 + tn];
            c[0][0] += a.x*b.x; c[0][1] += a.x*b.y; c[0][2] += a.x*b.z; c[0][3] += a.x*b.w;
            c[1][0] += a.y*b.x; c[1][1] += a.y*b.y; c[1][2] += a.y*b.z; c[1][3] += a.y*b.w;
            c[2][0] += a.z*b.x; c[2][1] += a.z*b.y; c[2][2] += a.z*b.z; c[2][3] += a.z*b.w;
            c[3][0] += a.w*b.x; c[3][1] += a.w*b.y; c[3][2] += a.w*b.z; c[3][3] += a.w*b.w;
        }
    }

    #pragma unroll
    for (int i = 0; i < 4; i++) {
        int r  = m0 + tm + i;
        int n  = r & (Nseq - 1);
        int bb = r >> 11;
        float v0 = c[i][0], v1 = c[i][1], v2 = c[i][2], v3 = c[i][3];
        if (mode == 2) {
            v0 = 1.f / (1.f + __expf(-v0));
            v1 = 1.f / (1.f + __expf(-v1));
            v2 = 1.f / (1.f + __expf(-v2));
            v3 = 1.f / (1.f + __expf(-v3));
        }
        float* op = out + (((size_t)(bb * Hn + head) * Nseq + n) * En + tn);
        op[0] = v0; op[1] = v1; op[2] = v2; op[3] = v3;
    }
}

// ---------------- Output GEMM: same k-major/float4 scheme ----------------
__global__ __launch_bounds__(256) void out_gemm(
    const float* __restrict__ A, const float* __restrict__ W,
    const float* __restrict__ bias, const float* __restrict__ resid,
    float* __restrict__ out)
{
    __shared__ float Asm[32 * 68];
    __shared__ float Bs [32 * 68];
    int tid = threadIdx.x;
    int m0  = blockIdx.x * 64;
    int n0  = blockIdx.y * 64;
    int tm = (tid >> 4) << 2;
    int tn = (tid & 15) << 2;
    float c[4][4] = {};

    for (int k0 = 0; k0 < Dmod; k0 += 32) {
        __syncthreads();
        #pragma unroll
        for (int l = 0; l < 8; l++) {
            int idx = l * 256 + tid;
            int am = idx >> 5, ak = idx & 31;
            Asm[ak * 68 + am] = A[(size_t)(m0 + am) * Dmod + k0 + ak];
            int bk = idx >> 6, bn = idx & 63;
            Bs[bk * 68 + bn] = W[(size_t)(k0 + bk) * Dmod + n0 + bn];
        }
        __syncthreads();
        #pragma unroll
        for (int kk = 0; kk < 32; kk++) {
            float4 a = *(const float4*)&Asm[kk * 68 + tm];
            float4 b = *(const float4*)&Bs [kk * 68 + tn];
            c[0][0] += a.x*b.x; c[0][1] += a.x*b.y; c[0][2] += a.x*b.z; c[0][3] += a.x*b.w;
            c[1][0] += a.y*b.x; c[1][1] += a.y*b.y; c[1][2] += a.y*b.z; c[1][3] += a.y*b.w;
            c[2][0] += a.z*b.x; c[2][1] += a.z*b.y; c[2][2] += a.z*b.z; c[2][3] += a.z*b.w;
            c[3][0] += a.w*b.x; c[3][1] += a.w*b.y; c[3][2] += a.w*b.z; c[3][3] += a.w*b.w;
        }
    }

    #pragma unroll
    for (int i = 0; i < 4; i++) {
        int r = m0 + tm + i;
        #pragma unroll
        for (int j = 0; j < 4; j++) {
            int col = n0 + tn + j;
            out[(size_t)r * Dmod + col] = c[i][j] + bias[col] + resid[(size_t)r * Dmod + col];
        }
    }
}

// ---------------- launch ----------------
extern "C" void kernel_launch(void* const* d_in, const int* in_sizes, int n_in,
                              void* d_out, int out_size)
{
    const float* x         = (const float*)d_in[0];
    const float* mask      = (const float*)d_in[1];
    const float* q_proj    = (const float*)d_in[2];
    const float* k_proj    = (const float*)d_in[3];
    const float* v_proj    = (const float*)d_in[4];
    const float* g_w       = (const float*)d_in[5];
    const float* gamma_in  = (const float*)d_in[6];
    const float* beta_in   = (const float*)d_in[7];
    const float* gamma_out = (const float*)d_in[8];
    const float* beta_out  = (const float*)d_in[9];
    const float* out_w     = (const float*)d_in[10];
    const float* out_b     = (const float*)d_in[11];

    float *xn, *qb, *kb, *vb, *gb, *ab, *tb;
    cudaGetSymbolAddress((void**)&xn, g_xn);
    cudaGetSymbolAddress((void**)&qb, g_q);
    cudaGetSymbolAddress((void**)&kb, g_k);
    cudaGetSymbolAddress((void**)&vb, g_v);
    cudaGetSymbolAddress((void**)&gb, g_g);
    cudaGetSymbolAddress((void**)&ab, g_att);
    cudaGetSymbolAddress((void**)&tb, g_tmp);

    ln_kernel<<<Mtot, 128>>>(x, gamma_in, beta_in, xn);

    // Reference RoPE rotates q,k identically per head (seq==H bug) -> cancels in q.k^T.
    dim3 ggrid(Mtot / 64, Hn);
    proj_gemm<<<ggrid, 256>>>(xn, q_proj, qb, 0);
    proj_gemm<<<ggrid, 256>>>(xn, k_proj, kb, 0);
    proj_gemm<<<ggrid, 256>>>(xn, v_proj, vb, 0);
    proj_gemm<<<ggrid, 256>>>(xn, g_w,    gb, 2);

    cudaFuncSetAttribute(attn_mma, cudaFuncAttributeMaxDynamicSharedMemorySize, ATT_SMEM);
    attn_mma<<<dim3(Nseq / 64, Bdim * Hn), 128, ATT_SMEM>>>(qb, kb, vb, gb, mask, ab);

    out_gemm<<<dim3(Mtot / 64, Dmod / 64), 256>>>(ab, out_w, out_b, x, tb);
    ln_kernel<<<Mtot, 128>>>(tb, gamma_out, beta_out, (float*)d_out);
}

// round 7
// speedup vs baseline: 1.1352x; 1.1352x over previous
#include <cuda_runtime.h>
#include <cuda_bf16.h>
#include <cstdint>

#define Bdim 4
#define Nseq 2048
#define Dmod 512
#define Hn   8
#define En   64
#define Mtot (Bdim*Nseq)
#define BHNE ((size_t)Bdim*Hn*Nseq*En)

__device__ float g_xn [(size_t)Mtot*Dmod];
__device__ float g_q  [BHNE];
__device__ float g_k  [BHNE];
__device__ float g_v  [BHNE];
__device__ float g_g  [BHNE];
__device__ float g_att[(size_t)Mtot*Dmod];
__device__ float g_tmp[(size_t)Mtot*Dmod];

// =============== helpers ===============
__device__ __forceinline__ void mma_bf16(float* c, const uint32_t* a, const uint32_t* b) {
    asm volatile("mma.sync.aligned.m16n8k16.row.col.f32.bf16.bf16.f32 "
        "{%0,%1,%2,%3}, {%4,%5,%6,%7}, {%8,%9}, {%0,%1,%2,%3};"
        : "+f"(c[0]), "+f"(c[1]), "+f"(c[2]), "+f"(c[3])
        : "r"(a[0]), "r"(a[1]), "r"(a[2]), "r"(a[3]), "r"(b[0]), "r"(b[1]));
}
__device__ __forceinline__ uint32_t packbf(__nv_bfloat16 lo, __nv_bfloat16 hi) {
    return ((uint32_t)__bfloat16_as_ushort(hi) << 16) | __bfloat16_as_ushort(lo);
}

#define ATT_T 4608   // 64 rows * 72 bf16 per staged tile
#define ATT_SMEM (6*ATT_T*2 + 256)

// ---------- warp-MMA flash attention (unchanged, proven at 9e-7) ----------
__global__ __launch_bounds__(128) void attn_mma(
    const float* __restrict__ Q, const float* __restrict__ K,
    const float* __restrict__ V, const float* __restrict__ G,
    const float* __restrict__ mask, float* __restrict__ out)
{
    extern __shared__ __nv_bfloat16 smb[];
    __nv_bfloat16 *Qh = smb,           *Ql = smb + ATT_T,
                  *Kh = smb + 2*ATT_T, *Kl = smb + 3*ATT_T,
                  *Vh = smb + 4*ATT_T, *Vl = smb + 5*ATT_T;   // Vh/Vl TRANSPOSED: [e][key]
    float* bias = (float*)(smb + 6*ATT_T);

    const int tid = threadIdx.x, wid = tid >> 5, lid = tid & 31;
    const int g = lid >> 2, qp = (lid & 3) * 2;
    const int qt = blockIdx.x, bh = blockIdx.y, bb = bh >> 3, hh = bh & 7;

    const float* Qg = Q + ((size_t)bh * Nseq + (size_t)qt * 64) * 64;
    const float* Kg = K + (size_t)bh * Nseq * 64;
    const float* Vg = V + (size_t)bh * Nseq * 64;

    for (int idx = tid; idx < 64 * 32; idx += 128) {
        int r = idx >> 5, cp = (idx & 31) * 2;
        float2 f = *(const float2*)(Qg + (size_t)r * 64 + cp);
        __nv_bfloat16 h0 = __float2bfloat16_rn(f.x), h1 = __float2bfloat16_rn(f.y);
        __nv_bfloat16 e0 = __float2bfloat16_rn(f.x - __bfloat162float(h0));
        __nv_bfloat16 e1 = __float2bfloat16_rn(f.y - __bfloat162float(h1));
        *(uint32_t*)(Qh + r * 72 + cp) = packbf(h0, h1);
        *(uint32_t*)(Ql + r * 72 + cp) = packbf(e0, e1);
    }
    __syncthreads();

    uint32_t qfh[4][4], qfl[4][4];
    {
        int ar = wid * 16 + g;
        #pragma unroll
        for (int kk = 0; kk < 4; kk++) {
            int c0 = kk * 16 + qp;
            qfh[kk][0] = *(const uint32_t*)(Qh + ar * 72 + c0);
            qfh[kk][1] = *(const uint32_t*)(Qh + (ar + 8) * 72 + c0);
            qfh[kk][2] = *(const uint32_t*)(Qh + ar * 72 + c0 + 8);
            qfh[kk][3] = *(const uint32_t*)(Qh + (ar + 8) * 72 + c0 + 8);
            qfl[kk][0] = *(const uint32_t*)(Ql + ar * 72 + c0);
            qfl[kk][1] = *(const uint32_t*)(Ql + (ar + 8) * 72 + c0);
            qfl[kk][2] = *(const uint32_t*)(Ql + ar * 72 + c0 + 8);
            qfl[kk][3] = *(const uint32_t*)(Ql + (ar + 8) * 72 + c0 + 8);
        }
    }

    float O[8][4];
    #pragma unroll
    for (int i = 0; i < 8; i++) { O[i][0]=0.f; O[i][1]=0.f; O[i][2]=0.f; O[i][3]=0.f; }
    float ps0 = 0.f, ps1 = 0.f;

    for (int t = 0; t < 32; t++) {
        __syncthreads();
        const float* Ks = Kg + (size_t)t * 64 * 64;
        const float* Vs = Vg + (size_t)t * 64 * 64;
        for (int idx = tid; idx < 64 * 32; idx += 128) {
            int r = idx >> 5, cp = (idx & 31) * 2;
            float2 f = *(const float2*)(Ks + (size_t)r * 64 + cp);
            __nv_bfloat16 h0 = __float2bfloat16_rn(f.x), h1 = __float2bfloat16_rn(f.y);
            __nv_bfloat16 e0 = __float2bfloat16_rn(f.x - __bfloat162float(h0));
            __nv_bfloat16 e1 = __float2bfloat16_rn(f.y - __bfloat162float(h1));
            *(uint32_t*)(Kh + r * 72 + cp) = packbf(h0, h1);
            *(uint32_t*)(Kl + r * 72 + cp) = packbf(e0, e1);
            float2 v = *(const float2*)(Vs + (size_t)r * 64 + cp);
            __nv_bfloat16 vh0 = __float2bfloat16_rn(v.x), vh1 = __float2bfloat16_rn(v.y);
            __nv_bfloat16 ve0 = __float2bfloat16_rn(v.x - __bfloat162float(vh0));
            __nv_bfloat16 ve1 = __float2bfloat16_rn(v.y - __bfloat162float(vh1));
            Vh[cp * 72 + r] = vh0; Vh[(cp + 1) * 72 + r] = vh1;
            Vl[cp * 72 + r] = ve0; Vl[(cp + 1) * 72 + r] = ve1;
        }
        if (tid < 64)
            bias[tid] = (mask[bb * Nseq + t * 64 + tid] > 0.f) ? 0.f : -1e9f;
        __syncthreads();

        float cS[8][4];
        #pragma unroll
        for (int i = 0; i < 8; i++) { cS[i][0]=0.f; cS[i][1]=0.f; cS[i][2]=0.f; cS[i][3]=0.f; }
        #pragma unroll
        for (int nt = 0; nt < 8; nt++) {
            int kb = (nt * 8 + g) * 72 + qp;
            #pragma unroll
            for (int kk = 0; kk < 4; kk++) {
                uint32_t b2h[2], b2l[2];
                const __nv_bfloat16* kp = Kh + kb + kk * 16;
                b2h[0] = *(const uint32_t*)kp; b2h[1] = *(const uint32_t*)(kp + 8);
                kp = Kl + kb + kk * 16;
                b2l[0] = *(const uint32_t*)kp; b2l[1] = *(const uint32_t*)(kp + 8);
                mma_bf16(cS[nt], qfh[kk], b2h);
                mma_bf16(cS[nt], qfh[kk], b2l);
                mma_bf16(cS[nt], qfl[kk], b2h);
            }
        }

        uint32_t ahi[4][4], alo[4][4];
        #pragma unroll
        for (int nt = 0; nt < 8; nt++) {
            float b0 = bias[nt * 8 + qp], b1 = bias[nt * 8 + qp + 1];
            float p0 = __expf(fmaf(cS[nt][0], 0.125f, b0));
            float p1 = __expf(fmaf(cS[nt][1], 0.125f, b1));
            float p2 = __expf(fmaf(cS[nt][2], 0.125f, b0));
            float p3 = __expf(fmaf(cS[nt][3], 0.125f, b1));
            ps0 += p0 + p1; ps1 += p2 + p3;
            __nv_bfloat16 h0 = __float2bfloat16_rn(p0), h1 = __float2bfloat16_rn(p1);
            __nv_bfloat16 h2 = __float2bfloat16_rn(p2), h3 = __float2bfloat16_rn(p3);
            __nv_bfloat16 l0 = __float2bfloat16_rn(p0 - __bfloat162float(h0));
            __nv_bfloat16 l1 = __float2bfloat16_rn(p1 - __bfloat162float(h1));
            __nv_bfloat16 l2 = __float2bfloat16_rn(p2 - __bfloat162float(h2));
            __nv_bfloat16 l3 = __float2bfloat16_rn(p3 - __bfloat162float(h3));
            int kk = nt >> 1, o = (nt & 1) * 2;
            ahi[kk][o]     = packbf(h0, h1);
            ahi[kk][o + 1] = packbf(h2, h3);
            alo[kk][o]     = packbf(l0, l1);
            alo[kk][o + 1] = packbf(l2, l3);
        }

        #pragma unroll
        for (int nt = 0; nt < 8; nt++) {
            int vb = (nt * 8 + g) * 72 + qp;
            #pragma unroll
            for (int kk = 0; kk < 4; kk++) {
                uint32_t b2h[2], b2l[2];
                const __nv_bfloat16* vp = Vh + vb + kk * 16;
                b2h[0] = *(const uint32_t*)vp; b2h[1] = *(const uint32_t*)(vp + 8);
                vp = Vl + vb + kk * 16;
                b2l[0] = *(const uint32_t*)vp; b2l[1] = *(const uint32_t*)(vp + 8);
                mma_bf16(O[nt], ahi[kk], b2h);
                mma_bf16(O[nt], ahi[kk], b2l);
                mma_bf16(O[nt], alo[kk], b2h);
            }
        }
    }

    ps0 += __shfl_xor_sync(0xffffffffu, ps0, 1);
    ps0 += __shfl_xor_sync(0xffffffffu, ps0, 2);
    ps1 += __shfl_xor_sync(0xffffffffu, ps1, 1);
    ps1 += __shfl_xor_sync(0xffffffffu, ps1, 2);

    int n0 = qt * 64 + wid * 16 + g, n1 = n0 + 8;
    float qm0 = (mask[bb * Nseq + n0] > 0.f) ? 1.f : 0.f;
    float qm1 = (mask[bb * Nseq + n1] > 0.f) ? 1.f : 0.f;
    float rc0 = (ps0 > 0.f) ? qm0 / ps0 : 0.f;
    float rc1 = (ps1 > 0.f) ? qm1 / ps1 : 0.f;

    const float* G0 = G + ((size_t)bh * Nseq + n0) * 64;
    const float* G1 = G + ((size_t)bh * Nseq + n1) * 64;
    float* O0 = out + ((size_t)bb * Nseq + n0) * Dmod + hh * 64;
    float* O1 = out + ((size_t)bb * Nseq + n1) * Dmod + hh * 64;
    #pragma unroll
    for (int nt = 0; nt < 8; nt++) {
        int col = nt * 8 + qp;
        float2 g0 = *(const float2*)(G0 + col);
        float2 g1 = *(const float2*)(G1 + col);
        float2 w0, w1;
        w0.x = O[nt][0] * rc0 * g0.x; w0.y = O[nt][1] * rc0 * g0.y;
        w1.x = O[nt][2] * rc1 * g1.x; w1.y = O[nt][3] * rc1 * g1.y;
        *(float2*)(O0 + col) = w0;
        *(float2*)(O1 + col) = w1;
    }
}

// ---------------- warp-MMA GEMM: C[64,64] tile, A[8192,512] x W ----------------
// Same fragment scheme as attention. W staged transposed [n][k] (like V).
// wmode: 0 = proj plain, 2 = proj sigmoid  (W indexed per head, out scatter BHNE)
//        1 = out_gemm (bias + residual, row-major out)
__global__ __launch_bounds__(128) void gemm_mma(
    const float* __restrict__ A, const float* __restrict__ W,
    const float* __restrict__ bias, const float* __restrict__ resid,
    float* __restrict__ out, int wmode)
{
    __shared__ __nv_bfloat16 Ah[ATT_T], Al[ATT_T], Wh[ATT_T], Wl[ATT_T];

    const int tid = threadIdx.x, wid = tid >> 5, lid = tid & 31;
    const int g = lid >> 2, qp = (lid & 3) * 2;
    const int m0 = blockIdx.x * 64;
    const int nb = blockIdx.y;                        // head (proj) or n-tile (out)
    const int Wn = (wmode == 1) ? Dmod : En;          // W row width
    const float* Wg = (wmode == 1) ? (W + nb * 64)    // out: [512,512], col block
                                   : (W + (size_t)nb * Dmod * En);  // proj head

    float cC[8][4];
    #pragma unroll
    for (int i = 0; i < 8; i++) { cC[i][0]=0.f; cC[i][1]=0.f; cC[i][2]=0.f; cC[i][3]=0.f; }

    for (int kc = 0; kc < 8; kc++) {
        __syncthreads();
        const int k0 = kc * 64;
        // stage A [64 m][64 k] hi/lo, k-contiguous stride 72 (same as attn Q)
        for (int idx = tid; idx < 64 * 32; idx += 128) {
            int r = idx >> 5, cp = (idx & 31) * 2;
            float2 f = *(const float2*)(A + (size_t)(m0 + r) * Dmod + k0 + cp);
            __nv_bfloat16 h0 = __float2bfloat16_rn(f.x), h1 = __float2bfloat16_rn(f.y);
            __nv_bfloat16 e0 = __float2bfloat16_rn(f.x - __bfloat162float(h0));
            __nv_bfloat16 e1 = __float2bfloat16_rn(f.y - __bfloat162float(h1));
            *(uint32_t*)(Ah + r * 72 + cp) = packbf(h0, h1);
            *(uint32_t*)(Al + r * 72 + cp) = packbf(e0, e1);
        }
        // stage W transposed -> [n][k] stride 72 (same as attn V)
        for (int idx = tid; idx < 64 * 32; idx += 128) {
            int r = idx >> 5, cp = (idx & 31) * 2;    // r = k within chunk, cp = n
            float2 f = *(const float2*)(Wg + (size_t)(k0 + r) * Wn + cp);
            __nv_bfloat16 h0 = __float2bfloat16_rn(f.x), h1 = __float2bfloat16_rn(f.y);
            __nv_bfloat16 e0 = __float2bfloat16_rn(f.x - __bfloat162float(h0));
            __nv_bfloat16 e1 = __float2bfloat16_rn(f.y - __bfloat162float(h1));
            Wh[cp * 72 + r] = h0; Wh[(cp + 1) * 72 + r] = h1;
            Wl[cp * 72 + r] = e0; Wl[(cp + 1) * 72 + r] = e1;
        }
        __syncthreads();

        uint32_t afh[4][4], afl[4][4];
        const int ar = wid * 16 + g;
        #pragma unroll
        for (int kk = 0; kk < 4; kk++) {
            int c0 = kk * 16 + qp;
            afh[kk][0] = *(const uint32_t*)(Ah + ar * 72 + c0);
            afh[kk][1] = *(const uint32_t*)(Ah + (ar + 8) * 72 + c0);
            afh[kk][2] = *(const uint32_t*)(Ah + ar * 72 + c0 + 8);
            afh[kk][3] = *(const uint32_t*)(Ah + (ar + 8) * 72 + c0 + 8);
            afl[kk][0] = *(const uint32_t*)(Al + ar * 72 + c0);
            afl[kk][1] = *(const uint32_t*)(Al + (ar + 8) * 72 + c0);
            afl[kk][2] = *(const uint32_t*)(Al + ar * 72 + c0 + 8);
            afl[kk][3] = *(const uint32_t*)(Al + (ar + 8) * 72 + c0 + 8);
        }

        #pragma unroll
        for (int nt = 0; nt < 8; nt++) {
            int wb = (nt * 8 + g) * 72 + qp;
            #pragma unroll
            for (int kk = 0; kk < 4; kk++) {
                uint32_t b2h[2], b2l[2];
                const __nv_bfloat16* wp = Wh + wb + kk * 16;
                b2h[0] = *(const uint32_t*)wp; b2h[1] = *(const uint32_t*)(wp + 8);
                wp = Wl + wb + kk * 16;
                b2l[0] = *(const uint32_t*)wp; b2l[1] = *(const uint32_t*)(wp + 8);
                mma_bf16(cC[nt], afh[kk], b2h);
                mma_bf16(cC[nt], afh[kk], b2l);
                mma_bf16(cC[nt], afl[kk], b2h);
            }
        }
    }

    // ---- epilogue ----
    const int r0 = m0 + wid * 16 + g, r1 = r0 + 8;
    if (wmode == 1) {
        #pragma unroll
        for (int nt = 0; nt < 8; nt++) {
            int col = nb * 64 + nt * 8 + qp;
            float2 w0, w1;
            w0.x = cC[nt][0] + bias[col]     + resid[(size_t)r0 * Dmod + col];
            w0.y = cC[nt][1] + bias[col + 1] + resid[(size_t)r0 * Dmod + col + 1];
            w1.x = cC[nt][2] + bias[col]     + resid[(size_t)r1 * Dmod + col];
            w1.y = cC[nt][3] + bias[col + 1] + resid[(size_t)r1 * Dmod + col + 1];
            *(float2*)(out + (size_t)r0 * Dmod + col) = w0;
            *(float2*)(out + (size_t)r1 * Dmod + col) = w1;
        }
    } else {
        int s0 = r0 & (Nseq - 1), b0 = r0 >> 11;
        int s1 = r1 & (Nseq - 1), b1 = r1 >> 11;
        float* p0 = out + (((size_t)(b0 * Hn + nb) * Nseq + s0) * En);
        float* p1 = out + (((size_t)(b1 * Hn + nb) * Nseq + s1) * En);
        #pragma unroll
        for (int nt = 0; nt < 8; nt++) {
            int col = nt * 8 + qp;
            float v0 = cC[nt][0], v1 = cC[nt][1], v2 = cC[nt][2], v3 = cC[nt][3];
            if (wmode == 2) {
                v0 = 1.f / (1.f + __expf(-v0));
                v1 = 1.f / (1.f + __expf(-v1));
                v2 = 1.f / (1.f + __expf(-v2));
                v3 = 1.f / (1.f + __expf(-v3));
            }
            *(float2*)(p0 + col) = make_float2(v0, v1);
            *(float2*)(p1 + col) = make_float2(v2, v3);
        }
    }
}

// ---------------- LayerNorm ----------------
__global__ void ln_kernel(const float* __restrict__ in,
                          const float* __restrict__ gamma,
                          const float* __restrict__ beta,
                          float* __restrict__ out)
{
    int row = blockIdx.x;
    int tid = threadIdx.x;
    const float4 v = ((const float4*)(in + (size_t)row * Dmod))[tid];
    __shared__ float red[4];

    float s = v.x + v.y + v.z + v.w;
    #pragma unroll
    for (int off = 16; off; off >>= 1) s += __shfl_xor_sync(0xffffffffu, s, off);
    if ((tid & 31) == 0) red[tid >> 5] = s;
    __syncthreads();
    float mean = (red[0] + red[1] + red[2] + red[3]) * (1.f / 512.f);

    float dx0 = v.x - mean, dx1 = v.y - mean, dx2 = v.z - mean, dx3 = v.w - mean;
    float ss = dx0*dx0 + dx1*dx1 + dx2*dx2 + dx3*dx3;
    __syncthreads();
    #pragma unroll
    for (int off = 16; off; off >>= 1) ss += __shfl_xor_sync(0xffffffffu, ss, off);
    if ((tid & 31) == 0) red[tid >> 5] = ss;
    __syncthreads();
    float var = (red[0] + red[1] + red[2] + red[3]) * (1.f / 512.f);
    float rstd = rsqrtf(var + 1e-6f);

    const float4 gm = ((const float4*)gamma)[tid];
    const float4 bt = ((const float4*)beta)[tid];
    float4 r;
    r.x = gm.x * dx0 * rstd + bt.x;
    r.y = gm.y * dx1 * rstd + bt.y;
    r.z = gm.z * dx2 * rstd + bt.z;
    r.w = gm.w * dx3 * rstd + bt.w;
    ((float4*)(out + (size_t)row * Dmod))[tid] = r;
}

// ---------------- launch ----------------
extern "C" void kernel_launch(void* const* d_in, const int* in_sizes, int n_in,
                              void* d_out, int out_size)
{
    const float* x         = (const float*)d_in[0];
    const float* mask      = (const float*)d_in[1];
    const float* q_proj    = (const float*)d_in[2];
    const float* k_proj    = (const float*)d_in[3];
    const float* v_proj    = (const float*)d_in[4];
    const float* g_w       = (const float*)d_in[5];
    const float* gamma_in  = (const float*)d_in[6];
    const float* beta_in   = (const float*)d_in[7];
    const float* gamma_out = (const float*)d_in[8];
    const float* beta_out  = (const float*)d_in[9];
    const float* out_w     = (const float*)d_in[10];
    const float* out_b     = (const float*)d_in[11];

    float *xn, *qb, *kb, *vb, *gb, *ab, *tb;
    cudaGetSymbolAddress((void**)&xn, g_xn);
    cudaGetSymbolAddress((void**)&qb, g_q);
    cudaGetSymbolAddress((void**)&kb, g_k);
    cudaGetSymbolAddress((void**)&vb, g_v);
    cudaGetSymbolAddress((void**)&gb, g_g);
    cudaGetSymbolAddress((void**)&ab, g_att);
    cudaGetSymbolAddress((void**)&tb, g_tmp);

    ln_kernel<<<Mtot, 128>>>(x, gamma_in, beta_in, xn);

    // Reference RoPE rotates q,k identically per head (seq==H bug) -> cancels in q.k^T.
    dim3 ggrid(Mtot / 64, Hn);
    gemm_mma<<<ggrid, 128>>>(xn, q_proj, nullptr, nullptr, qb, 0);
    gemm_mma<<<ggrid, 128>>>(xn, k_proj, nullptr, nullptr, kb, 0);
    gemm_mma<<<ggrid, 128>>>(xn, v_proj, nullptr, nullptr, vb, 0);
    gemm_mma<<<ggrid, 128>>>(xn, g_w,    nullptr, nullptr, gb, 2);

    cudaFuncSetAttribute(attn_mma, cudaFuncAttributeMaxDynamicSharedMemorySize, ATT_SMEM);
    attn_mma<<<dim3(Nseq / 64, Bdim * Hn), 128, ATT_SMEM>>>(qb, kb, vb, gb, mask, ab);

    gemm_mma<<<dim3(Mtot / 64, Dmod / 64), 128>>>(ab, out_w, out_b, x, tb, 1);
    ln_kernel<<<Mtot, 128>>>(tb, gamma_out, beta_out, (float*)d_out);
}

// round 8
// speedup vs baseline: 1.8402x; 1.6211x over previous
#include <cuda_runtime.h>
#include <cuda_bf16.h>
#include <cstdint>

#define Bdim 4
#define Nseq 2048
#define Dmod 512
#define Hn   8
#define En   64
#define Mtot (Bdim*Nseq)
#define BHNE ((size_t)Bdim*Hn*Nseq*En)

typedef __nv_bfloat16 bf;

// ---------------- scratch (device globals) ----------------
__device__ bf    xn_h[(size_t)Mtot*Dmod], xn_l[(size_t)Mtot*Dmod];
__device__ bf    q_h [BHNE], q_l [BHNE];
__device__ bf    k_h [BHNE], k_l [BHNE];
__device__ bf    v_h [BHNE], v_l [BHNE];          // TRANSPOSED: [bh][e][n]
__device__ bf    at_h[(size_t)Mtot*Dmod], at_l[(size_t)Mtot*Dmod];
__device__ float g_gate[BHNE];
__device__ float g_tmp [(size_t)Mtot*Dmod];
__device__ bf    wq_h[Hn*En*Dmod], wq_l[Hn*En*Dmod];   // [h*64+e][d]
__device__ bf    wk_h[Hn*En*Dmod], wk_l[Hn*En*Dmod];
__device__ bf    wv_h[Hn*En*Dmod], wv_l[Hn*En*Dmod];
__device__ bf    wg_h[Hn*En*Dmod], wg_l[Hn*En*Dmod];
__device__ bf    wo_h[Dmod*Dmod],  wo_l[Dmod*Dmod];    // [n][k]

// =============== helpers ===============
__device__ __forceinline__ void mma_bf16(float* c, const uint32_t* a, const uint32_t* b) {
    asm volatile("mma.sync.aligned.m16n8k16.row.col.f32.bf16.bf16.f32 "
        "{%0,%1,%2,%3}, {%4,%5,%6,%7}, {%8,%9}, {%0,%1,%2,%3};"
        : "+f"(c[0]), "+f"(c[1]), "+f"(c[2]), "+f"(c[3])
        : "r"(a[0]), "r"(a[1]), "r"(a[2]), "r"(a[3]), "r"(b[0]), "r"(b[1]));
}
__device__ __forceinline__ uint32_t packbf(bf lo, bf hi) {
    return ((uint32_t)__bfloat16_as_ushort(hi) << 16) | __bfloat16_as_ushort(lo);
}
__device__ __forceinline__ void split(float v, bf& h, bf& l) {
    h = __float2bfloat16_rn(v);
    l = __float2bfloat16_rn(v - __bfloat162float(h));
}

#define ATT_T 4608   // 64 rows * 72 bf16 per staged tile

// ---------------- LN -> hi/lo bf16 (input LN) ----------------
__global__ void ln_hilo(const float* __restrict__ in,
                        const float* __restrict__ gamma,
                        const float* __restrict__ beta,
                        bf* __restrict__ oh, bf* __restrict__ ol)
{
    int row = blockIdx.x, tid = threadIdx.x;
    const float4 v = ((const float4*)(in + (size_t)row * Dmod))[tid];
    __shared__ float red[4];

    float s = v.x + v.y + v.z + v.w;
    #pragma unroll
    for (int off = 16; off; off >>= 1) s += __shfl_xor_sync(0xffffffffu, s, off);
    if ((tid & 31) == 0) red[tid >> 5] = s;
    __syncthreads();
    float mean = (red[0] + red[1] + red[2] + red[3]) * (1.f / 512.f);

    float dx0 = v.x - mean, dx1 = v.y - mean, dx2 = v.z - mean, dx3 = v.w - mean;
    float ss = dx0*dx0 + dx1*dx1 + dx2*dx2 + dx3*dx3;
    __syncthreads();
    #pragma unroll
    for (int off = 16; off; off >>= 1) ss += __shfl_xor_sync(0xffffffffu, ss, off);
    if ((tid & 31) == 0) red[tid >> 5] = ss;
    __syncthreads();
    float var = (red[0] + red[1] + red[2] + red[3]) * (1.f / 512.f);
    float rstd = rsqrtf(var + 1e-6f);

    const float4 gm = ((const float4*)gamma)[tid];
    const float4 bt = ((const float4*)beta)[tid];
    float r0 = gm.x * dx0 * rstd + bt.x;
    float r1 = gm.y * dx1 * rstd + bt.y;
    float r2 = gm.z * dx2 * rstd + bt.z;
    float r3 = gm.w * dx3 * rstd + bt.w;
    bf h0,l0,h1,l1,h2,l2,h3,l3;
    split(r0,h0,l0); split(r1,h1,l1); split(r2,h2,l2); split(r3,h3,l3);
    uint32_t* ph = (uint32_t*)(oh + (size_t)row * Dmod) + tid * 2;
    uint32_t* pl = (uint32_t*)(ol + (size_t)row * Dmod) + tid * 2;
    ph[0] = packbf(h0,h1); ph[1] = packbf(h2,h3);
    pl[0] = packbf(l0,l1); pl[1] = packbf(l2,l3);
}

// ---------------- plain fp32 LN (output) ----------------
__global__ void ln_kernel(const float* __restrict__ in,
                          const float* __restrict__ gamma,
                          const float* __restrict__ beta,
                          float* __restrict__ out)
{
    int row = blockIdx.x, tid = threadIdx.x;
    const float4 v = ((const float4*)(in + (size_t)row * Dmod))[tid];
    __shared__ float red[4];

    float s = v.x + v.y + v.z + v.w;
    #pragma unroll
    for (int off = 16; off; off >>= 1) s += __shfl_xor_sync(0xffffffffu, s, off);
    if ((tid & 31) == 0) red[tid >> 5] = s;
    __syncthreads();
    float mean = (red[0] + red[1] + red[2] + red[3]) * (1.f / 512.f);

    float dx0 = v.x - mean, dx1 = v.y - mean, dx2 = v.z - mean, dx3 = v.w - mean;
    float ss = dx0*dx0 + dx1*dx1 + dx2*dx2 + dx3*dx3;
    __syncthreads();
    #pragma unroll
    for (int off = 16; off; off >>= 1) ss += __shfl_xor_sync(0xffffffffu, ss, off);
    if ((tid & 31) == 0) red[tid >> 5] = ss;
    __syncthreads();
    float var = (red[0] + red[1] + red[2] + red[3]) * (1.f / 512.f);
    float rstd = rsqrtf(var + 1e-6f);

    const float4 gm = ((const float4*)gamma)[tid];
    const float4 bt = ((const float4*)beta)[tid];
    float4 r;
    r.x = gm.x * dx0 * rstd + bt.x;
    r.y = gm.y * dx1 * rstd + bt.y;
    r.z = gm.z * dx2 * rstd + bt.z;
    r.w = gm.w * dx3 * rstd + bt.w;
    ((float4*)(out + (size_t)row * Dmod))[tid] = r;
}

// ---------------- weight split + transpose ----------------
// proj W[h,d,e] -> [h*64+e][d]   (262144 elements)
__global__ void wcvt_proj(const float* __restrict__ W, bf* __restrict__ wh, bf* __restrict__ wl)
{
    int idx = blockIdx.x * 256 + threadIdx.x;
    int e = idx & 63, d = (idx >> 6) & 511, h = idx >> 15;
    float v = W[idx];
    bf hh, ll; split(v, hh, ll);
    int o = ((h * 64 + e) << 9) + d;
    wh[o] = hh; wl[o] = ll;
}
// out_w [k][n] 512x512 -> [n][k]
__global__ void wcvt_out(const float* __restrict__ W, bf* __restrict__ wh, bf* __restrict__ wl)
{
    int idx = blockIdx.x * 256 + threadIdx.x;
    int n = idx & 511, k = idx >> 9;
    float v = W[idx];
    bf hh, ll; split(v, hh, ll);
    wh[n * 512 + k] = hh; wl[n * 512 + k] = ll;
}

// ---------------- warp-MMA GEMM, bf16-staged ----------------
// A: [8192][512] hi/lo (m-major); W: [512][512] hi/lo (n-major, n = nb*64+local).
// mode 0: q/k  -> hi/lo [bh][n][e]
// mode 1: v    -> hi/lo [bh][e][n] (transposed)
// mode 2: gate -> sigmoid fp32 [bh][n][e]
// mode 3: out  -> fp32 + bias + resid, row-major [m][512]
__global__ __launch_bounds__(128) void gemm_bf(
    const bf* __restrict__ Ahg, const bf* __restrict__ Alg,
    const bf* __restrict__ Whg, const bf* __restrict__ Wlg,
    const float* __restrict__ bias, const float* __restrict__ resid,
    float* __restrict__ outf, bf* __restrict__ oh, bf* __restrict__ ol,
    int mode)
{
    __shared__ bf Ah[ATT_T], Al[ATT_T], Wh[ATT_T], Wl[ATT_T];

    const int tid = threadIdx.x, wid = tid >> 5, lid = tid & 31;
    const int g = lid >> 2, qp = (lid & 3) * 2;
    const int m0 = blockIdx.x * 64;
    const int nb = blockIdx.y;

    float cC[8][4];
    #pragma unroll
    for (int i = 0; i < 8; i++) { cC[i][0]=0.f; cC[i][1]=0.f; cC[i][2]=0.f; cC[i][3]=0.f; }

    for (int kc = 0; kc < 8; kc++) {
        const int k0 = kc * 64;
        __syncthreads();
        #pragma unroll
        for (int i = tid; i < 512; i += 128) {
            int r = i >> 3, c = i & 7;
            *(uint4*)(Ah + r * 72 + c * 8) = *(const uint4*)(Ahg + (size_t)(m0 + r) * 512 + k0 + c * 8);
            *(uint4*)(Al + r * 72 + c * 8) = *(const uint4*)(Alg + (size_t)(m0 + r) * 512 + k0 + c * 8);
            *(uint4*)(Wh + r * 72 + c * 8) = *(const uint4*)(Whg + (size_t)(nb * 64 + r) * 512 + k0 + c * 8);
            *(uint4*)(Wl + r * 72 + c * 8) = *(const uint4*)(Wlg + (size_t)(nb * 64 + r) * 512 + k0 + c * 8);
        }
        __syncthreads();

        uint32_t afh[4][4], afl[4][4];
        const int ar = wid * 16 + g;
        #pragma unroll
        for (int kk = 0; kk < 4; kk++) {
            int c0 = kk * 16 + qp;
            afh[kk][0] = *(const uint32_t*)(Ah + ar * 72 + c0);
            afh[kk][1] = *(const uint32_t*)(Ah + (ar + 8) * 72 + c0);
            afh[kk][2] = *(const uint32_t*)(Ah + ar * 72 + c0 + 8);
            afh[kk][3] = *(const uint32_t*)(Ah + (ar + 8) * 72 + c0 + 8);
            afl[kk][0] = *(const uint32_t*)(Al + ar * 72 + c0);
            afl[kk][1] = *(const uint32_t*)(Al + (ar + 8) * 72 + c0);
            afl[kk][2] = *(const uint32_t*)(Al + ar * 72 + c0 + 8);
            afl[kk][3] = *(const uint32_t*)(Al + (ar + 8) * 72 + c0 + 8);
        }

        #pragma unroll
        for (int nt = 0; nt < 8; nt++) {
            int wb = (nt * 8 + g) * 72 + qp;
            #pragma unroll
            for (int kk = 0; kk < 4; kk++) {
                uint32_t b2h[2], b2l[2];
                const bf* wp = Wh + wb + kk * 16;
                b2h[0] = *(const uint32_t*)wp; b2h[1] = *(const uint32_t*)(wp + 8);
                wp = Wl + wb + kk * 16;
                b2l[0] = *(const uint32_t*)wp; b2l[1] = *(const uint32_t*)(wp + 8);
                mma_bf16(cC[nt], afh[kk], b2h);
                mma_bf16(cC[nt], afh[kk], b2l);
                mma_bf16(cC[nt], afl[kk], b2h);
            }
        }
    }

    const int r0 = m0 + wid * 16 + g, r1 = r0 + 8;
    if (mode == 3) {
        #pragma unroll
        for (int nt = 0; nt < 8; nt++) {
            int col = nb * 64 + nt * 8 + qp;
            float2 w0, w1;
            w0.x = cC[nt][0] + bias[col]     + resid[(size_t)r0 * Dmod + col];
            w0.y = cC[nt][1] + bias[col + 1] + resid[(size_t)r0 * Dmod + col + 1];
            w1.x = cC[nt][2] + bias[col]     + resid[(size_t)r1 * Dmod + col];
            w1.y = cC[nt][3] + bias[col + 1] + resid[(size_t)r1 * Dmod + col + 1];
            *(float2*)(outf + (size_t)r0 * Dmod + col) = w0;
            *(float2*)(outf + (size_t)r1 * Dmod + col) = w1;
        }
        return;
    }
    int s0 = r0 & (Nseq - 1), b0 = r0 >> 11;
    int s1 = r1 & (Nseq - 1), b1 = r1 >> 11;
    if (mode == 0) {
        uint32_t* p0h = (uint32_t*)(oh + (((size_t)(b0 * Hn + nb) * Nseq + s0) * En));
        uint32_t* p0l = (uint32_t*)(ol + (((size_t)(b0 * Hn + nb) * Nseq + s0) * En));
        uint32_t* p1h = (uint32_t*)(oh + (((size_t)(b1 * Hn + nb) * Nseq + s1) * En));
        uint32_t* p1l = (uint32_t*)(ol + (((size_t)(b1 * Hn + nb) * Nseq + s1) * En));
        #pragma unroll
        for (int nt = 0; nt < 8; nt++) {
            int cw = (nt * 8 + qp) >> 1;
            bf h0,l0,h1,l1,h2,l2,h3,l3;
            split(cC[nt][0],h0,l0); split(cC[nt][1],h1,l1);
            split(cC[nt][2],h2,l2); split(cC[nt][3],h3,l3);
            p0h[cw] = packbf(h0,h1); p0l[cw] = packbf(l0,l1);
            p1h[cw] = packbf(h2,h3); p1l[cw] = packbf(l2,l3);
        }
    } else if (mode == 1) {
        // V transposed: [bh][e][n]
        #pragma unroll
        for (int nt = 0; nt < 8; nt++) {
            int col = nt * 8 + qp;
            bf h0,l0,h1,l1,h2,l2,h3,l3;
            split(cC[nt][0],h0,l0); split(cC[nt][1],h1,l1);
            split(cC[nt][2],h2,l2); split(cC[nt][3],h3,l3);
            size_t e0 = ((size_t)(b0 * Hn + nb) * En + col) * Nseq;
            size_t e1 = ((size_t)(b0 * Hn + nb) * En + col + 1) * Nseq;
            oh[e0 + s0] = h0; oh[e1 + s0] = h1;
            ol[e0 + s0] = l0; ol[e1 + s0] = l1;
            size_t f0 = ((size_t)(b1 * Hn + nb) * En + col) * Nseq;
            size_t f1 = ((size_t)(b1 * Hn + nb) * En + col + 1) * Nseq;
            oh[f0 + s1] = h2; oh[f1 + s1] = h3;
            ol[f0 + s1] = l2; ol[f1 + s1] = l3;
        }
    } else {  // mode 2: sigmoid gate fp32
        float* p0 = outf + (((size_t)(b0 * Hn + nb) * Nseq + s0) * En);
        float* p1 = outf + (((size_t)(b1 * Hn + nb) * Nseq + s1) * En);
        #pragma unroll
        for (int nt = 0; nt < 8; nt++) {
            int col = nt * 8 + qp;
            *(float2*)(p0 + col) = make_float2(1.f/(1.f+__expf(-cC[nt][0])), 1.f/(1.f+__expf(-cC[nt][1])));
            *(float2*)(p1 + col) = make_float2(1.f/(1.f+__expf(-cC[nt][2])), 1.f/(1.f+__expf(-cC[nt][3])));
        }
    }
}

#define ATT_SMEM (6*ATT_T*2 + 256)

// ---------------- attention: bf16-staged, hi/lo output ----------------
__global__ __launch_bounds__(128) void attn_mma(
    const bf* __restrict__ Qhg, const bf* __restrict__ Qlg,
    const bf* __restrict__ Khg, const bf* __restrict__ Klg,
    const bf* __restrict__ Vhg, const bf* __restrict__ Vlg,   // [bh][e][n]
    const float* __restrict__ G, const float* __restrict__ mask,
    bf* __restrict__ Oh, bf* __restrict__ Ol)
{
    extern __shared__ bf smb[];
    bf *Qh = smb,           *Ql = smb + ATT_T,
       *Kh = smb + 2*ATT_T, *Kl = smb + 3*ATT_T,
       *Vh = smb + 4*ATT_T, *Vl = smb + 5*ATT_T;   // [e][key]
    float* bias = (float*)(smb + 6*ATT_T);

    const int tid = threadIdx.x, wid = tid >> 5, lid = tid & 31;
    const int g = lid >> 2, qp = (lid & 3) * 2;
    const int qt = blockIdx.x, bh = blockIdx.y, bb = bh >> 3, hh = bh & 7;

    const bf* Qhb = Qhg + ((size_t)bh * Nseq + (size_t)qt * 64) * 64;
    const bf* Qlb = Qlg + ((size_t)bh * Nseq + (size_t)qt * 64) * 64;
    const bf* Khb = Khg + (size_t)bh * Nseq * 64;
    const bf* Klb = Klg + (size_t)bh * Nseq * 64;
    const bf* Vhb = Vhg + (size_t)bh * En * Nseq;
    const bf* Vlb = Vlg + (size_t)bh * En * Nseq;

    #pragma unroll
    for (int i = tid; i < 512; i += 128) {
        int r = i >> 3, c = i & 7;
        *(uint4*)(Qh + r * 72 + c * 8) = *(const uint4*)(Qhb + (size_t)r * 64 + c * 8);
        *(uint4*)(Ql + r * 72 + c * 8) = *(const uint4*)(Qlb + (size_t)r * 64 + c * 8);
    }
    __syncthreads();

    uint32_t qfh[4][4], qfl[4][4];
    {
        int ar = wid * 16 + g;
        #pragma unroll
        for (int kk = 0; kk < 4; kk++) {
            int c0 = kk * 16 + qp;
            qfh[kk][0] = *(const uint32_t*)(Qh + ar * 72 + c0);
            qfh[kk][1] = *(const uint32_t*)(Qh + (ar + 8) * 72 + c0);
            qfh[kk][2] = *(const uint32_t*)(Qh + ar * 72 + c0 + 8);
            qfh[kk][3] = *(const uint32_t*)(Qh + (ar + 8) * 72 + c0 + 8);
            qfl[kk][0] = *(const uint32_t*)(Ql + ar * 72 + c0);
            qfl[kk][1] = *(const uint32_t*)(Ql + (ar + 8) * 72 + c0);
            qfl[kk][2] = *(const uint32_t*)(Ql + ar * 72 + c0 + 8);
            qfl[kk][3] = *(const uint32_t*)(Ql + (ar + 8) * 72 + c0 + 8);
        }
    }

    float O[8][4];
    #pragma unroll
    for (int i = 0; i < 8; i++) { O[i][0]=0.f; O[i][1]=0.f; O[i][2]=0.f; O[i][3]=0.f; }
    float ps0 = 0.f, ps1 = 0.f;

    for (int t = 0; t < 32; t++) {
        __syncthreads();
        #pragma unroll
        for (int i = tid; i < 512; i += 128) {
            int r = i >> 3, c = i & 7;
            *(uint4*)(Kh + r * 72 + c * 8) = *(const uint4*)(Khb + (size_t)(t * 64 + r) * 64 + c * 8);
            *(uint4*)(Kl + r * 72 + c * 8) = *(const uint4*)(Klb + (size_t)(t * 64 + r) * 64 + c * 8);
            *(uint4*)(Vh + r * 72 + c * 8) = *(const uint4*)(Vhb + (size_t)r * Nseq + t * 64 + c * 8);
            *(uint4*)(Vl + r * 72 + c * 8) = *(const uint4*)(Vlb + (size_t)r * Nseq + t * 64 + c * 8);
        }
        if (tid < 64)
            bias[tid] = (mask[bb * Nseq + t * 64 + tid] > 0.f) ? 0.f : -1e9f;
        __syncthreads();

        float cS[8][4];
        #pragma unroll
        for (int i = 0; i < 8; i++) { cS[i][0]=0.f; cS[i][1]=0.f; cS[i][2]=0.f; cS[i][3]=0.f; }
        #pragma unroll
        for (int nt = 0; nt < 8; nt++) {
            int kb = (nt * 8 + g) * 72 + qp;
            #pragma unroll
            for (int kk = 0; kk < 4; kk++) {
                uint32_t b2h[2], b2l[2];
                const bf* kp = Kh + kb + kk * 16;
                b2h[0] = *(const uint32_t*)kp; b2h[1] = *(const uint32_t*)(kp + 8);
                kp = Kl + kb + kk * 16;
                b2l[0] = *(const uint32_t*)kp; b2l[1] = *(const uint32_t*)(kp + 8);
                mma_bf16(cS[nt], qfh[kk], b2h);
                mma_bf16(cS[nt], qfh[kk], b2l);
                mma_bf16(cS[nt], qfl[kk], b2h);
            }
        }

        uint32_t ahi[4][4], alo[4][4];
        #pragma unroll
        for (int nt = 0; nt < 8; nt++) {
            float b0 = bias[nt * 8 + qp], b1 = bias[nt * 8 + qp + 1];
            float p0 = __expf(fmaf(cS[nt][0], 0.125f, b0));
            float p1 = __expf(fmaf(cS[nt][1], 0.125f, b1));
            float p2 = __expf(fmaf(cS[nt][2], 0.125f, b0));
            float p3 = __expf(fmaf(cS[nt][3], 0.125f, b1));
            ps0 += p0 + p1; ps1 += p2 + p3;
            bf h0,l0,h1,l1,h2,l2,h3,l3;
            split(p0,h0,l0); split(p1,h1,l1); split(p2,h2,l2); split(p3,h3,l3);
            int kk = nt >> 1, o = (nt & 1) * 2;
            ahi[kk][o]     = packbf(h0, h1);
            ahi[kk][o + 1] = packbf(h2, h3);
            alo[kk][o]     = packbf(l0, l1);
            alo[kk][o + 1] = packbf(l2, l3);
        }

        #pragma unroll
        for (int nt = 0; nt < 8; nt++) {
            int vb = (nt * 8 + g) * 72 + qp;
            #pragma unroll
            for (int kk = 0; kk < 4; kk++) {
                uint32_t b2h[2], b2l[2];
                const bf* vp = Vh + vb + kk * 16;
                b2h[0] = *(const uint32_t*)vp; b2h[1] = *(const uint32_t*)(vp + 8);
                vp = Vl + vb + kk * 16;
                b2l[0] = *(const uint32_t*)vp; b2l[1] = *(const uint32_t*)(vp + 8);
                mma_bf16(O[nt], ahi[kk], b2h);
                mma_bf16(O[nt], ahi[kk], b2l);
                mma_bf16(O[nt], alo[kk], b2h);
            }
        }
    }

    ps0 += __shfl_xor_sync(0xffffffffu, ps0, 1);
    ps0 += __shfl_xor_sync(0xffffffffu, ps0, 2);
    ps1 += __shfl_xor_sync(0xffffffffu, ps1, 1);
    ps1 += __shfl_xor_sync(0xffffffffu, ps1, 2);

    int n0 = qt * 64 + wid * 16 + g, n1 = n0 + 8;
    float qm0 = (mask[bb * Nseq + n0] > 0.f) ? 1.f : 0.f;
    float qm1 = (mask[bb * Nseq + n1] > 0.f) ? 1.f : 0.f;
    float rc0 = (ps0 > 0.f) ? qm0 / ps0 : 0.f;
    float rc1 = (ps1 > 0.f) ? qm1 / ps1 : 0.f;

    const float* G0 = G + ((size_t)bh * Nseq + n0) * 64;
    const float* G1 = G + ((size_t)bh * Nseq + n1) * 64;
    uint32_t* o0h = (uint32_t*)(Oh + ((size_t)bb * Nseq + n0) * Dmod + hh * 64);
    uint32_t* o0l = (uint32_t*)(Ol + ((size_t)bb * Nseq + n0) * Dmod + hh * 64);
    uint32_t* o1h = (uint32_t*)(Oh + ((size_t)bb * Nseq + n1) * Dmod + hh * 64);
    uint32_t* o1l = (uint32_t*)(Ol + ((size_t)bb * Nseq + n1) * Dmod + hh * 64);
    #pragma unroll
    for (int nt = 0; nt < 8; nt++) {
        int col = nt * 8 + qp, cw = col >> 1;
        float2 g0 = *(const float2*)(G0 + col);
        float2 g1 = *(const float2*)(G1 + col);
        bf h0,l0,h1,l1,h2,l2,h3,l3;
        split(O[nt][0] * rc0 * g0.x, h0, l0);
        split(O[nt][1] * rc0 * g0.y, h1, l1);
        split(O[nt][2] * rc1 * g1.x, h2, l2);
        split(O[nt][3] * rc1 * g1.y, h3, l3);
        o0h[cw] = packbf(h0,h1); o0l[cw] = packbf(l0,l1);
        o1h[cw] = packbf(h2,h3); o1l[cw] = packbf(l2,l3);
    }
}

// ---------------- launch ----------------
extern "C" void kernel_launch(void* const* d_in, const int* in_sizes, int n_in,
                              void* d_out, int out_size)
{
    const float* x         = (const float*)d_in[0];
    const float* mask      = (const float*)d_in[1];
    const float* q_proj    = (const float*)d_in[2];
    const float* k_proj    = (const float*)d_in[3];
    const float* v_proj    = (const float*)d_in[4];
    const float* g_w       = (const float*)d_in[5];
    const float* gamma_in  = (const float*)d_in[6];
    const float* beta_in   = (const float*)d_in[7];
    const float* gamma_out = (const float*)d_in[8];
    const float* beta_out  = (const float*)d_in[9];
    const float* out_w     = (const float*)d_in[10];
    const float* out_b     = (const float*)d_in[11];

    bf *xnh,*xnl,*qh,*ql,*kh,*kl,*vh,*vl,*ath,*atl;
    bf *wqh,*wql,*wkh,*wkl,*wvh,*wvl,*wgh,*wgl,*woh,*wol;
    float *gate,*tmp;
    cudaGetSymbolAddress((void**)&xnh, xn_h); cudaGetSymbolAddress((void**)&xnl, xn_l);
    cudaGetSymbolAddress((void**)&qh, q_h);   cudaGetSymbolAddress((void**)&ql, q_l);
    cudaGetSymbolAddress((void**)&kh, k_h);   cudaGetSymbolAddress((void**)&kl, k_l);
    cudaGetSymbolAddress((void**)&vh, v_h);   cudaGetSymbolAddress((void**)&vl, v_l);
    cudaGetSymbolAddress((void**)&ath, at_h); cudaGetSymbolAddress((void**)&atl, at_l);
    cudaGetSymbolAddress((void**)&wqh, wq_h); cudaGetSymbolAddress((void**)&wql, wq_l);
    cudaGetSymbolAddress((void**)&wkh, wk_h); cudaGetSymbolAddress((void**)&wkl, wk_l);
    cudaGetSymbolAddress((void**)&wvh, wv_h); cudaGetSymbolAddress((void**)&wvl, wv_l);
    cudaGetSymbolAddress((void**)&wgh, wg_h); cudaGetSymbolAddress((void**)&wgl, wg_l);
    cudaGetSymbolAddress((void**)&woh, wo_h); cudaGetSymbolAddress((void**)&wol, wo_l);
    cudaGetSymbolAddress((void**)&gate, g_gate);
    cudaGetSymbolAddress((void**)&tmp,  g_tmp);

    // LN -> hi/lo; weights split+transpose (cheap, per launch)
    ln_hilo<<<Mtot, 128>>>(x, gamma_in, beta_in, xnh, xnl);
    wcvt_proj<<<1024, 256>>>(q_proj, wqh, wql);
    wcvt_proj<<<1024, 256>>>(k_proj, wkh, wkl);
    wcvt_proj<<<1024, 256>>>(v_proj, wvh, wvl);
    wcvt_proj<<<1024, 256>>>(g_w,    wgh, wgl);
    wcvt_out <<<1024, 256>>>(out_w,  woh, wol);

    // Reference RoPE rotates q,k identically per head (seq==H bug) -> cancels in q.k^T.
    dim3 ggrid(Mtot / 64, Hn);
    gemm_bf<<<ggrid, 128>>>(xnh, xnl, wqh, wql, nullptr, nullptr, nullptr, qh, ql, 0);
    gemm_bf<<<ggrid, 128>>>(xnh, xnl, wkh, wkl, nullptr, nullptr, nullptr, kh, kl, 0);
    gemm_bf<<<ggrid, 128>>>(xnh, xnl, wvh, wvl, nullptr, nullptr, nullptr, vh, vl, 1);
    gemm_bf<<<ggrid, 128>>>(xnh, xnl, wgh, wgl, nullptr, nullptr, gate,    nullptr, nullptr, 2);

    cudaFuncSetAttribute(attn_mma, cudaFuncAttributeMaxDynamicSharedMemorySize, ATT_SMEM);
    attn_mma<<<dim3(Nseq / 64, Bdim * Hn), 128, ATT_SMEM>>>(qh, ql, kh, kl, vh, vl, gate, mask, ath, atl);

    gemm_bf<<<dim3(Mtot / 64, Dmod / 64), 128>>>(ath, atl, woh, wol, out_b, x, tmp, nullptr, nullptr, 3);
    ln_kernel<<<Mtot, 128>>>(tmp, gamma_out, beta_out, (float*)d_out);
}

// round 9
// speedup vs baseline: 1.8656x; 1.0138x over previous
#include <cuda_runtime.h>
#include <cuda_bf16.h>
#include <cstdint>

#define Bdim 4
#define Nseq 2048
#define Dmod 512
#define Hn   8
#define En   64
#define Mtot (Bdim*Nseq)
#define BHNE ((size_t)Bdim*Hn*Nseq*En)

typedef __nv_bfloat16 bf;

// ---------------- scratch (device globals) ----------------
__device__ bf    xn_h[(size_t)Mtot*Dmod], xn_l[(size_t)Mtot*Dmod];
__device__ bf    q_h [BHNE], q_l [BHNE];
__device__ bf    k_h [BHNE], k_l [BHNE];
__device__ bf    v_h [BHNE], v_l [BHNE];          // TRANSPOSED: [bh][e][n]
__device__ bf    at_h[(size_t)Mtot*Dmod], at_l[(size_t)Mtot*Dmod];
__device__ float g_gate[BHNE];
__device__ float g_tmp [(size_t)Mtot*Dmod];
__device__ bf    wq_h[Hn*En*Dmod], wq_l[Hn*En*Dmod];   // [h*64+e][d]
__device__ bf    wk_h[Hn*En*Dmod], wk_l[Hn*En*Dmod];
__device__ bf    wv_h[Hn*En*Dmod], wv_l[Hn*En*Dmod];
__device__ bf    wg_h[Hn*En*Dmod], wg_l[Hn*En*Dmod];
__device__ bf    wo_h[Dmod*Dmod],  wo_l[Dmod*Dmod];    // [n][k]

// =============== helpers ===============
__device__ __forceinline__ void mma_bf16(float* c, const uint32_t* a, const uint32_t* b) {
    asm volatile("mma.sync.aligned.m16n8k16.row.col.f32.bf16.bf16.f32 "
        "{%0,%1,%2,%3}, {%4,%5,%6,%7}, {%8,%9}, {%0,%1,%2,%3};"
        : "+f"(c[0]), "+f"(c[1]), "+f"(c[2]), "+f"(c[3])
        : "r"(a[0]), "r"(a[1]), "r"(a[2]), "r"(a[3]), "r"(b[0]), "r"(b[1]));
}
__device__ __forceinline__ uint32_t packbf(bf lo, bf hi) {
    return ((uint32_t)__bfloat16_as_ushort(hi) << 16) | __bfloat16_as_ushort(lo);
}
__device__ __forceinline__ void split(float v, bf& h, bf& l) {
    h = __float2bfloat16_rn(v);
    l = __float2bfloat16_rn(v - __bfloat162float(h));
}
__device__ __forceinline__ void cp16(uint32_t s, const void* g) {
    asm volatile("cp.async.cg.shared.global [%0], [%1], 16;" :: "r"(s), "l"(g));
}
#define CP_COMMIT() asm volatile("cp.async.commit_group;" ::: "memory")
#define CP_WAIT1()  asm volatile("cp.async.wait_group 1;" ::: "memory")
#define CP_WAIT0()  asm volatile("cp.async.wait_group 0;" ::: "memory")

#define ATT_T 4608   // 64 rows * 72 bf16 per staged tile
#define TB    (ATT_T*2)   // tile bytes

// ---------------- LN -> hi/lo bf16 (input LN) ----------------
__global__ void ln_hilo(const float* __restrict__ in,
                        const float* __restrict__ gamma,
                        const float* __restrict__ beta,
                        bf* __restrict__ oh, bf* __restrict__ ol)
{
    int row = blockIdx.x, tid = threadIdx.x;
    const float4 v = ((const float4*)(in + (size_t)row * Dmod))[tid];
    __shared__ float red[4];

    float s = v.x + v.y + v.z + v.w;
    #pragma unroll
    for (int off = 16; off; off >>= 1) s += __shfl_xor_sync(0xffffffffu, s, off);
    if ((tid & 31) == 0) red[tid >> 5] = s;
    __syncthreads();
    float mean = (red[0] + red[1] + red[2] + red[3]) * (1.f / 512.f);

    float dx0 = v.x - mean, dx1 = v.y - mean, dx2 = v.z - mean, dx3 = v.w - mean;
    float ss = dx0*dx0 + dx1*dx1 + dx2*dx2 + dx3*dx3;
    __syncthreads();
    #pragma unroll
    for (int off = 16; off; off >>= 1) ss += __shfl_xor_sync(0xffffffffu, ss, off);
    if ((tid & 31) == 0) red[tid >> 5] = ss;
    __syncthreads();
    float var = (red[0] + red[1] + red[2] + red[3]) * (1.f / 512.f);
    float rstd = rsqrtf(var + 1e-6f);

    const float4 gm = ((const float4*)gamma)[tid];
    const float4 bt = ((const float4*)beta)[tid];
    float r0 = gm.x * dx0 * rstd + bt.x;
    float r1 = gm.y * dx1 * rstd + bt.y;
    float r2 = gm.z * dx2 * rstd + bt.z;
    float r3 = gm.w * dx3 * rstd + bt.w;
    bf h0,l0,h1,l1,h2,l2,h3,l3;
    split(r0,h0,l0); split(r1,h1,l1); split(r2,h2,l2); split(r3,h3,l3);
    uint32_t* ph = (uint32_t*)(oh + (size_t)row * Dmod) + tid * 2;
    uint32_t* pl = (uint32_t*)(ol + (size_t)row * Dmod) + tid * 2;
    ph[0] = packbf(h0,h1); ph[1] = packbf(h2,h3);
    pl[0] = packbf(l0,l1); pl[1] = packbf(l2,l3);
}

// ---------------- plain fp32 LN (output) ----------------
__global__ void ln_kernel(const float* __restrict__ in,
                          const float* __restrict__ gamma,
                          const float* __restrict__ beta,
                          float* __restrict__ out)
{
    int row = blockIdx.x, tid = threadIdx.x;
    const float4 v = ((const float4*)(in + (size_t)row * Dmod))[tid];
    __shared__ float red[4];

    float s = v.x + v.y + v.z + v.w;
    #pragma unroll
    for (int off = 16; off; off >>= 1) s += __shfl_xor_sync(0xffffffffu, s, off);
    if ((tid & 31) == 0) red[tid >> 5] = s;
    __syncthreads();
    float mean = (red[0] + red[1] + red[2] + red[3]) * (1.f / 512.f);

    float dx0 = v.x - mean, dx1 = v.y - mean, dx2 = v.z - mean, dx3 = v.w - mean;
    float ss = dx0*dx0 + dx1*dx1 + dx2*dx2 + dx3*dx3;
    __syncthreads();
    #pragma unroll
    for (int off = 16; off; off >>= 1) ss += __shfl_xor_sync(0xffffffffu, ss, off);
    if ((tid & 31) == 0) red[tid >> 5] = ss;
    __syncthreads();
    float var = (red[0] + red[1] + red[2] + red[3]) * (1.f / 512.f);
    float rstd = rsqrtf(var + 1e-6f);

    const float4 gm = ((const float4*)gamma)[tid];
    const float4 bt = ((const float4*)beta)[tid];
    float4 r;
    r.x = gm.x * dx0 * rstd + bt.x;
    r.y = gm.y * dx1 * rstd + bt.y;
    r.z = gm.z * dx2 * rstd + bt.z;
    r.w = gm.w * dx3 * rstd + bt.w;
    ((float4*)(out + (size_t)row * Dmod))[tid] = r;
}

// ---------------- all weight splits in ONE launch ----------------
__global__ void wcvt_all(const float* __restrict__ qw, const float* __restrict__ kw,
                         const float* __restrict__ vw, const float* __restrict__ gw,
                         const float* __restrict__ ow,
                         bf* qh, bf* ql, bf* kh, bf* kl, bf* vh, bf* vl,
                         bf* gh, bf* gl, bf* oh, bf* ol)
{
    int idx = blockIdx.x * 256 + threadIdx.x;
    int w = blockIdx.y;
    if (w < 4) {
        const float* W = (w == 0) ? qw : (w == 1) ? kw : (w == 2) ? vw : gw;
        bf* H = (w == 0) ? qh : (w == 1) ? kh : (w == 2) ? vh : gh;
        bf* L = (w == 0) ? ql : (w == 1) ? kl : (w == 2) ? vl : gl;
        int e = idx & 63, d = (idx >> 6) & 511, h = idx >> 15;
        float v = W[idx];
        bf hh, ll; split(v, hh, ll);
        int o = ((h * 64 + e) << 9) + d;
        H[o] = hh; L[o] = ll;
    } else {
        int n = idx & 511, k = idx >> 9;
        float v = ow[idx];
        bf hh, ll; split(v, hh, ll);
        oh[n * 512 + k] = hh; ol[n * 512 + k] = ll;
    }
}

// ---------------- warp-MMA GEMM, cp.async double-buffered ----------------
// smem: 2 bufs x [Ah|Al|Wh|Wl] x ATT_T
#define GEMM_SMEM (2 * 4 * TB)
__global__ __launch_bounds__(128) void gemm_bf(
    const bf* __restrict__ Ahg, const bf* __restrict__ Alg,
    const bf* __restrict__ Whg, const bf* __restrict__ Wlg,
    const float* __restrict__ bias, const float* __restrict__ resid,
    float* __restrict__ outf, bf* __restrict__ oh, bf* __restrict__ ol,
    int mode)
{
    extern __shared__ bf sm[];
    const int tid = threadIdx.x, wid = tid >> 5, lid = tid & 31;
    const int g = lid >> 2, qp = (lid & 3) * 2;
    const int m0 = blockIdx.x * 64;
    const int nb = blockIdx.y;
    const uint32_t smb = (uint32_t)__cvta_generic_to_shared(sm);

    auto stage = [&](int kc, int b) {
        const int k0 = kc * 64;
        uint32_t base = smb + b * 4 * TB;
        #pragma unroll
        for (int i = tid; i < 512; i += 128) {
            int r = i >> 3, c = (i & 7) * 8;
            uint32_t off = (uint32_t)(r * 72 + c) * 2;
            cp16(base + off,          Ahg + (size_t)(m0 + r) * 512 + k0 + c);
            cp16(base + TB + off,     Alg + (size_t)(m0 + r) * 512 + k0 + c);
            cp16(base + 2*TB + off,   Whg + (size_t)(nb * 64 + r) * 512 + k0 + c);
            cp16(base + 3*TB + off,   Wlg + (size_t)(nb * 64 + r) * 512 + k0 + c);
        }
    };

    float cC[8][4];
    #pragma unroll
    for (int i = 0; i < 8; i++) { cC[i][0]=0.f; cC[i][1]=0.f; cC[i][2]=0.f; cC[i][3]=0.f; }

    stage(0, 0); CP_COMMIT();

    for (int kc = 0; kc < 8; kc++) {
        const int buf = kc & 1;
        if (kc + 1 < 8) { stage(kc + 1, buf ^ 1); CP_COMMIT(); CP_WAIT1(); }
        else CP_WAIT0();
        __syncthreads();

        const bf* Ah = sm + buf * 4 * ATT_T;
        const bf* Al = Ah + ATT_T;
        const bf* Wh = Ah + 2 * ATT_T;
        const bf* Wl = Ah + 3 * ATT_T;

        uint32_t afh[4][4], afl[4][4];
        const int ar = wid * 16 + g;
        #pragma unroll
        for (int kk = 0; kk < 4; kk++) {
            int c0 = kk * 16 + qp;
            afh[kk][0] = *(const uint32_t*)(Ah + ar * 72 + c0);
            afh[kk][1] = *(const uint32_t*)(Ah + (ar + 8) * 72 + c0);
            afh[kk][2] = *(const uint32_t*)(Ah + ar * 72 + c0 + 8);
            afh[kk][3] = *(const uint32_t*)(Ah + (ar + 8) * 72 + c0 + 8);
            afl[kk][0] = *(const uint32_t*)(Al + ar * 72 + c0);
            afl[kk][1] = *(const uint32_t*)(Al + (ar + 8) * 72 + c0);
            afl[kk][2] = *(const uint32_t*)(Al + ar * 72 + c0 + 8);
            afl[kk][3] = *(const uint32_t*)(Al + (ar + 8) * 72 + c0 + 8);
        }

        #pragma unroll
        for (int nt = 0; nt < 8; nt++) {
            int wb = (nt * 8 + g) * 72 + qp;
            #pragma unroll
            for (int kk = 0; kk < 4; kk++) {
                uint32_t b2h[2], b2l[2];
                const bf* wp = Wh + wb + kk * 16;
                b2h[0] = *(const uint32_t*)wp; b2h[1] = *(const uint32_t*)(wp + 8);
                wp = Wl + wb + kk * 16;
                b2l[0] = *(const uint32_t*)wp; b2l[1] = *(const uint32_t*)(wp + 8);
                mma_bf16(cC[nt], afh[kk], b2h);
                mma_bf16(cC[nt], afh[kk], b2l);
                mma_bf16(cC[nt], afl[kk], b2h);
            }
        }
        __syncthreads();
    }

    const int r0 = m0 + wid * 16 + g, r1 = r0 + 8;
    if (mode == 3) {
        #pragma unroll
        for (int nt = 0; nt < 8; nt++) {
            int col = nb * 64 + nt * 8 + qp;
            float2 w0, w1;
            w0.x = cC[nt][0] + bias[col]     + resid[(size_t)r0 * Dmod + col];
            w0.y = cC[nt][1] + bias[col + 1] + resid[(size_t)r0 * Dmod + col + 1];
            w1.x = cC[nt][2] + bias[col]     + resid[(size_t)r1 * Dmod + col];
            w1.y = cC[nt][3] + bias[col + 1] + resid[(size_t)r1 * Dmod + col + 1];
            *(float2*)(outf + (size_t)r0 * Dmod + col) = w0;
            *(float2*)(outf + (size_t)r1 * Dmod + col) = w1;
        }
        return;
    }
    int s0 = r0 & (Nseq - 1), b0 = r0 >> 11;
    int s1 = r1 & (Nseq - 1), b1 = r1 >> 11;
    if (mode == 0) {
        uint32_t* p0h = (uint32_t*)(oh + (((size_t)(b0 * Hn + nb) * Nseq + s0) * En));
        uint32_t* p0l = (uint32_t*)(ol + (((size_t)(b0 * Hn + nb) * Nseq + s0) * En));
        uint32_t* p1h = (uint32_t*)(oh + (((size_t)(b1 * Hn + nb) * Nseq + s1) * En));
        uint32_t* p1l = (uint32_t*)(ol + (((size_t)(b1 * Hn + nb) * Nseq + s1) * En));
        #pragma unroll
        for (int nt = 0; nt < 8; nt++) {
            int cw = (nt * 8 + qp) >> 1;
            bf h0,l0,h1,l1,h2,l2,h3,l3;
            split(cC[nt][0],h0,l0); split(cC[nt][1],h1,l1);
            split(cC[nt][2],h2,l2); split(cC[nt][3],h3,l3);
            p0h[cw] = packbf(h0,h1); p0l[cw] = packbf(l0,l1);
            p1h[cw] = packbf(h2,h3); p1l[cw] = packbf(l2,l3);
        }
    } else if (mode == 1) {
        #pragma unroll
        for (int nt = 0; nt < 8; nt++) {
            int col = nt * 8 + qp;
            bf h0,l0,h1,l1,h2,l2,h3,l3;
            split(cC[nt][0],h0,l0); split(cC[nt][1],h1,l1);
            split(cC[nt][2],h2,l2); split(cC[nt][3],h3,l3);
            size_t e0 = ((size_t)(b0 * Hn + nb) * En + col) * Nseq;
            size_t e1 = ((size_t)(b0 * Hn + nb) * En + col + 1) * Nseq;
            oh[e0 + s0] = h0; oh[e1 + s0] = h1;
            ol[e0 + s0] = l0; ol[e1 + s0] = l1;
            size_t f0 = ((size_t)(b1 * Hn + nb) * En + col) * Nseq;
            size_t f1 = ((size_t)(b1 * Hn + nb) * En + col + 1) * Nseq;
            oh[f0 + s1] = h2; oh[f1 + s1] = h3;
            ol[f0 + s1] = l2; ol[f1 + s1] = l3;
        }
    } else {
        float* p0 = outf + (((size_t)(b0 * Hn + nb) * Nseq + s0) * En);
        float* p1 = outf + (((size_t)(b1 * Hn + nb) * Nseq + s1) * En);
        #pragma unroll
        for (int nt = 0; nt < 8; nt++) {
            int col = nt * 8 + qp;
            *(float2*)(p0 + col) = make_float2(1.f/(1.f+__expf(-cC[nt][0])), 1.f/(1.f+__expf(-cC[nt][1])));
            *(float2*)(p1 + col) = make_float2(1.f/(1.f+__expf(-cC[nt][2])), 1.f/(1.f+__expf(-cC[nt][3])));
        }
    }
}

// ---------------- attention: cp.async double-buffered K/V, bias hoisted ----------------
// smem bf units: Qh 0, Ql ATT_T; KV buf b at 2*ATT_T + b*4*ATT_T (Kh,Kl,Vh,Vl);
// bias float[2048] at 10*ATT_T.
#define ATT_SMEM (10 * TB + 2048 * 4)
__global__ __launch_bounds__(128) void attn_mma(
    const bf* __restrict__ Qhg, const bf* __restrict__ Qlg,
    const bf* __restrict__ Khg, const bf* __restrict__ Klg,
    const bf* __restrict__ Vhg, const bf* __restrict__ Vlg,   // [bh][e][n]
    const float* __restrict__ G, const float* __restrict__ mask,
    bf* __restrict__ Oh, bf* __restrict__ Ol)
{
    extern __shared__ bf smb[];
    bf* Qh = smb;
    bf* Ql = smb + ATT_T;
    float* biasS = (float*)(smb + 10 * ATT_T);

    const int tid = threadIdx.x, wid = tid >> 5, lid = tid & 31;
    const int g = lid >> 2, qp = (lid & 3) * 2;
    const int qt = blockIdx.x, bh = blockIdx.y, bb = bh >> 3, hh = bh & 7;
    const uint32_t smu = (uint32_t)__cvta_generic_to_shared(smb);

    const bf* Qhb = Qhg + ((size_t)bh * Nseq + (size_t)qt * 64) * 64;
    const bf* Qlb = Qlg + ((size_t)bh * Nseq + (size_t)qt * 64) * 64;
    const bf* Khb = Khg + (size_t)bh * Nseq * 64;
    const bf* Klb = Klg + (size_t)bh * Nseq * 64;
    const bf* Vhb = Vhg + (size_t)bh * En * Nseq;
    const bf* Vlb = Vlg + (size_t)bh * En * Nseq;

    auto stageKV = [&](int t, int b) {
        uint32_t base = smu + 2 * TB + b * 4 * TB;
        #pragma unroll
        for (int i = tid; i < 512; i += 128) {
            int r = i >> 3, c = (i & 7) * 8;
            uint32_t off = (uint32_t)(r * 72 + c) * 2;
            cp16(base + off,          Khb + (size_t)(t * 64 + r) * 64 + c);
            cp16(base + TB + off,     Klb + (size_t)(t * 64 + r) * 64 + c);
            cp16(base + 2*TB + off,   Vhb + (size_t)r * Nseq + t * 64 + c);
            cp16(base + 3*TB + off,   Vlb + (size_t)r * Nseq + t * 64 + c);
        }
    };

    // stage Q + full mask bias
    #pragma unroll
    for (int i = tid; i < 512; i += 128) {
        int r = i >> 3, c = (i & 7) * 8;
        *(uint4*)(Qh + r * 72 + c) = *(const uint4*)(Qhb + (size_t)r * 64 + c);
        *(uint4*)(Ql + r * 72 + c) = *(const uint4*)(Qlb + (size_t)r * 64 + c);
    }
    for (int j = tid; j < Nseq; j += 128)
        biasS[j] = (mask[bb * Nseq + j] > 0.f) ? 0.f : -1e9f;
    stageKV(0, 0); CP_COMMIT();
    __syncthreads();

    uint32_t qfh[4][4], qfl[4][4];
    {
        int ar = wid * 16 + g;
        #pragma unroll
        for (int kk = 0; kk < 4; kk++) {
            int c0 = kk * 16 + qp;
            qfh[kk][0] = *(const uint32_t*)(Qh + ar * 72 + c0);
            qfh[kk][1] = *(const uint32_t*)(Qh + (ar + 8) * 72 + c0);
            qfh[kk][2] = *(const uint32_t*)(Qh + ar * 72 + c0 + 8);
            qfh[kk][3] = *(const uint32_t*)(Qh + (ar + 8) * 72 + c0 + 8);
            qfl[kk][0] = *(const uint32_t*)(Ql + ar * 72 + c0);
            qfl[kk][1] = *(const uint32_t*)(Ql + (ar + 8) * 72 + c0);
            qfl[kk][2] = *(const uint32_t*)(Ql + ar * 72 + c0 + 8);
            qfl[kk][3] = *(const uint32_t*)(Ql + (ar + 8) * 72 + c0 + 8);
        }
    }

    float O[8][4];
    #pragma unroll
    for (int i = 0; i < 8; i++) { O[i][0]=0.f; O[i][1]=0.f; O[i][2]=0.f; O[i][3]=0.f; }
    float ps0 = 0.f, ps1 = 0.f;

    for (int t = 0; t < 32; t++) {
        const int buf = t & 1;
        if (t + 1 < 32) { stageKV(t + 1, buf ^ 1); CP_COMMIT(); CP_WAIT1(); }
        else CP_WAIT0();
        __syncthreads();

        const bf* Kh = smb + 2 * ATT_T + buf * 4 * ATT_T;
        const bf* Kl = Kh + ATT_T;
        const bf* Vh = Kh + 2 * ATT_T;
        const bf* Vl = Kh + 3 * ATT_T;
        const float* bias = biasS + t * 64;

        float cS[8][4];
        #pragma unroll
        for (int i = 0; i < 8; i++) { cS[i][0]=0.f; cS[i][1]=0.f; cS[i][2]=0.f; cS[i][3]=0.f; }
        #pragma unroll
        for (int nt = 0; nt < 8; nt++) {
            int kb = (nt * 8 + g) * 72 + qp;
            #pragma unroll
            for (int kk = 0; kk < 4; kk++) {
                uint32_t b2h[2], b2l[2];
                const bf* kp = Kh + kb + kk * 16;
                b2h[0] = *(const uint32_t*)kp; b2h[1] = *(const uint32_t*)(kp + 8);
                kp = Kl + kb + kk * 16;
                b2l[0] = *(const uint32_t*)kp; b2l[1] = *(const uint32_t*)(kp + 8);
                mma_bf16(cS[nt], qfh[kk], b2h);
                mma_bf16(cS[nt], qfh[kk], b2l);
                mma_bf16(cS[nt], qfl[kk], b2h);
            }
        }

        uint32_t ahi[4][4], alo[4][4];
        #pragma unroll
        for (int nt = 0; nt < 8; nt++) {
            float b0 = bias[nt * 8 + qp], b1 = bias[nt * 8 + qp + 1];
            float p0 = __expf(fmaf(cS[nt][0], 0.125f, b0));
            float p1 = __expf(fmaf(cS[nt][1], 0.125f, b1));
            float p2 = __expf(fmaf(cS[nt][2], 0.125f, b0));
            float p3 = __expf(fmaf(cS[nt][3], 0.125f, b1));
            ps0 += p0 + p1; ps1 += p2 + p3;
            bf h0,l0,h1,l1,h2,l2,h3,l3;
            split(p0,h0,l0); split(p1,h1,l1); split(p2,h2,l2); split(p3,h3,l3);
            int kk = nt >> 1, o = (nt & 1) * 2;
            ahi[kk][o]     = packbf(h0, h1);
            ahi[kk][o + 1] = packbf(h2, h3);
            alo[kk][o]     = packbf(l0, l1);
            alo[kk][o + 1] = packbf(l2, l3);
        }

        #pragma unroll
        for (int nt = 0; nt < 8; nt++) {
            int vb = (nt * 8 + g) * 72 + qp;
            #pragma unroll
            for (int kk = 0; kk < 4; kk++) {
                uint32_t b2h[2], b2l[2];
                const bf* vp = Vh + vb + kk * 16;
                b2h[0] = *(const uint32_t*)vp; b2h[1] = *(const uint32_t*)(vp + 8);
                vp = Vl + vb + kk * 16;
                b2l[0] = *(const uint32_t*)vp; b2l[1] = *(const uint32_t*)(vp + 8);
                mma_bf16(O[nt], ahi[kk], b2h);
                mma_bf16(O[nt], ahi[kk], b2l);
                mma_bf16(O[nt], alo[kk], b2h);
            }
        }
        __syncthreads();
    }

    ps0 += __shfl_xor_sync(0xffffffffu, ps0, 1);
    ps0 += __shfl_xor_sync(0xffffffffu, ps0, 2);
    ps1 += __shfl_xor_sync(0xffffffffu, ps1, 1);
    ps1 += __shfl_xor_sync(0xffffffffu, ps1, 2);

    int n0 = qt * 64 + wid * 16 + g, n1 = n0 + 8;
    float qm0 = (mask[bb * Nseq + n0] > 0.f) ? 1.f : 0.f;
    float qm1 = (mask[bb * Nseq + n1] > 0.f) ? 1.f : 0.f;
    float rc0 = (ps0 > 0.f) ? qm0 / ps0 : 0.f;
    float rc1 = (ps1 > 0.f) ? qm1 / ps1 : 0.f;

    const float* G0 = G + ((size_t)bh * Nseq + n0) * 64;
    const float* G1 = G + ((size_t)bh * Nseq + n1) * 64;
    uint32_t* o0h = (uint32_t*)(Oh + ((size_t)bb * Nseq + n0) * Dmod + hh * 64);
    uint32_t* o0l = (uint32_t*)(Ol + ((size_t)bb * Nseq + n0) * Dmod + hh * 64);
    uint32_t* o1h = (uint32_t*)(Oh + ((size_t)bb * Nseq + n1) * Dmod + hh * 64);
    uint32_t* o1l = (uint32_t*)(Ol + ((size_t)bb * Nseq + n1) * Dmod + hh * 64);
    #pragma unroll
    for (int nt = 0; nt < 8; nt++) {
        int col = nt * 8 + qp, cw = col >> 1;
        float2 g0 = *(const float2*)(G0 + col);
        float2 g1 = *(const float2*)(G1 + col);
        bf h0,l0,h1,l1,h2,l2,h3,l3;
        split(O[nt][0] * rc0 * g0.x, h0, l0);
        split(O[nt][1] * rc0 * g0.y, h1, l1);
        split(O[nt][2] * rc1 * g1.x, h2, l2);
        split(O[nt][3] * rc1 * g1.y, h3, l3);
        o0h[cw] = packbf(h0,h1); o0l[cw] = packbf(l0,l1);
        o1h[cw] = packbf(h2,h3); o1l[cw] = packbf(l2,l3);
    }
}

// ---------------- launch ----------------
extern "C" void kernel_launch(void* const* d_in, const int* in_sizes, int n_in,
                              void* d_out, int out_size)
{
    const float* x         = (const float*)d_in[0];
    const float* mask      = (const float*)d_in[1];
    const float* q_proj    = (const float*)d_in[2];
    const float* k_proj    = (const float*)d_in[3];
    const float* v_proj    = (const float*)d_in[4];
    const float* g_w       = (const float*)d_in[5];
    const float* gamma_in  = (const float*)d_in[6];
    const float* beta_in   = (const float*)d_in[7];
    const float* gamma_out = (const float*)d_in[8];
    const float* beta_out  = (const float*)d_in[9];
    const float* out_w     = (const float*)d_in[10];
    const float* out_b     = (const float*)d_in[11];

    bf *xnh,*xnl,*qh,*ql,*kh,*kl,*vh,*vl,*ath,*atl;
    bf *wqh,*wql,*wkh,*wkl,*wvh,*wvl,*wgh,*wgl,*woh,*wol;
    float *gate,*tmp;
    cudaGetSymbolAddress((void**)&xnh, xn_h); cudaGetSymbolAddress((void**)&xnl, xn_l);
    cudaGetSymbolAddress((void**)&qh, q_h);   cudaGetSymbolAddress((void**)&ql, q_l);
    cudaGetSymbolAddress((void**)&kh, k_h);   cudaGetSymbolAddress((void**)&kl, k_l);
    cudaGetSymbolAddress((void**)&vh, v_h);   cudaGetSymbolAddress((void**)&vl, v_l);
    cudaGetSymbolAddress((void**)&ath, at_h); cudaGetSymbolAddress((void**)&atl, at_l);
    cudaGetSymbolAddress((void**)&wqh, wq_h); cudaGetSymbolAddress((void**)&wql, wq_l);
    cudaGetSymbolAddress((void**)&wkh, wk_h); cudaGetSymbolAddress((void**)&wkl, wk_l);
    cudaGetSymbolAddress((void**)&wvh, wv_h); cudaGetSymbolAddress((void**)&wvl, wv_l);
    cudaGetSymbolAddress((void**)&wgh, wg_h); cudaGetSymbolAddress((void**)&wgl, wg_l);
    cudaGetSymbolAddress((void**)&woh, wo_h); cudaGetSymbolAddress((void**)&wol, wo_l);
    cudaGetSymbolAddress((void**)&gate, g_gate);
    cudaGetSymbolAddress((void**)&tmp,  g_tmp);

    static int attr_set = 0;
    if (!attr_set) {
        cudaFuncSetAttribute(gemm_bf,  cudaFuncAttributeMaxDynamicSharedMemorySize, GEMM_SMEM);
        cudaFuncSetAttribute(attn_mma, cudaFuncAttributeMaxDynamicSharedMemorySize, ATT_SMEM);
        attr_set = 1;
    }

    ln_hilo<<<Mtot, 128>>>(x, gamma_in, beta_in, xnh, xnl);
    wcvt_all<<<dim3(1024, 5), 256>>>(q_proj, k_proj, v_proj, g_w, out_w,
                                     wqh, wql, wkh, wkl, wvh, wvl, wgh, wgl, woh, wol);

    // Reference RoPE rotates q,k identically per head (seq==H bug) -> cancels in q.k^T.
    dim3 ggrid(Mtot / 64, Hn);
    gemm_bf<<<ggrid, 128, GEMM_SMEM>>>(xnh, xnl, wqh, wql, nullptr, nullptr, nullptr, qh, ql, 0);
    gemm_bf<<<ggrid, 128, GEMM_SMEM>>>(xnh, xnl, wkh, wkl, nullptr, nullptr, nullptr, kh, kl, 0);
    gemm_bf<<<ggrid, 128, GEMM_SMEM>>>(xnh, xnl, wvh, wvl, nullptr, nullptr, nullptr, vh, vl, 1);
    gemm_bf<<<ggrid, 128, GEMM_SMEM>>>(xnh, xnl, wgh, wgl, nullptr, nullptr, gate,    nullptr, nullptr, 2);

    attn_mma<<<dim3(Nseq / 64, Bdim * Hn), 128, ATT_SMEM>>>(qh, ql, kh, kl, vh, vl, gate, mask, ath, atl);

    gemm_bf<<<dim3(Mtot / 64, Dmod / 64), 128, GEMM_SMEM>>>(ath, atl, woh, wol, out_b, x, tmp, nullptr, nullptr, 3);
    ln_kernel<<<Mtot, 128>>>(tmp, gamma_out, beta_out, (float*)d_out);
}